// round 8
// baseline (speedup 1.0000x reference)
#include <cuda_runtime.h>
#include <cuda_bf16.h>
#include <cuda_fp16.h>
#include <cstdint>

#define NN   50000
#define EE   800000
#define PP   3
#define HH   4
#define DD   64
#define CIN  256          // H*D = in_size
#define K2   512          // split-K (hi|lo concat)
#define EPS  1e-5f
#define SLOPE 0.2f

// ---------------- device scratch (static, no allocation) ----------------
__device__ __align__(256) __half g_f16 [(size_t)PP*NN*CIN];   // fp16 projected features
__device__ __align__(256) float g_accum[(size_t)PP*NN*CIN];
__device__ __align__(256) __nv_bfloat16 g_h2 [(size_t)NN*K2];
__device__ __align__(256) __nv_bfloat16 g_w2t[(size_t)PP*CIN*K2];
__device__ __align__(16)  float g_el   [PP*NN*HH];
__device__ __align__(16)  float g_er   [PP*NN*HH];
__device__ int g_deg   [PP*NN];
__device__ int g_rowptr[PP*(NN+1)];
__device__ int g_cur   [PP*NN];
__device__ int g_bsum  [PP*64];
__device__ int g_boff  [PP*64];
__device__ int g_eidx  [(size_t)PP*EE];
__device__ int g_esrc  [(size_t)PP*EE];
__device__ float g_sum  [PP*CIN];
__device__ float g_sumsq[PP*CIN];
__device__ float g_scale[PP*CIN];
__device__ float g_shift[PP*CIN];

// ---------------- K0: zero small scratch ----------------
__global__ void k_zero() {
    int i = blockIdx.x * blockDim.x + threadIdx.x;
    if (i < PP * NN) g_deg[i] = 0;
    if (i < PP * CIN) { g_sum[i] = 0.f; g_sumsq[i] = 0.f; }
}

// ---------------- Kw: semantic weights ----------------
__global__ void k_w(const float* __restrict__ mask, float* __restrict__ wout) {
    int n = blockIdx.x * blockDim.x + threadIdx.x;
    if (n >= NN) return;
    float m0 = mask[n*PP+0], m1 = mask[n*PP+1], m2 = mask[n*PP+2];
    float inv = 1.f / (m0 + m1 + m2);
    wout[n*PP+0] = m0 * inv;
    wout[n*PP+1] = m1 * inv;
    wout[n*PP+2] = m2 * inv;
}

// ---------------- conversions: fp32 -> bf16 hi/lo split ----------------
__global__ void k_cvt_h(const float* __restrict__ h) {
    size_t i = (size_t)blockIdx.x * blockDim.x + threadIdx.x;
    if (i >= (size_t)NN * CIN) return;
    size_t m = i >> 8, k = i & 255;
    float v = h[i];
    __nv_bfloat16 hi = __float2bfloat16(v);
    __nv_bfloat16 lo = __float2bfloat16(v - __bfloat162float(hi));
    g_h2[m * K2 + k]       = hi;
    g_h2[m * K2 + 256 + k] = lo;
}
__global__ void k_cvt_w(const float* __restrict__ fc) {
    int i = blockIdx.x * blockDim.x + threadIdx.x;
    if (i >= PP * CIN * CIN) return;
    int p = i >> 16, rem = i & 65535;
    int k = rem >> 8, n = rem & 255;
    float v = fc[i];
    __nv_bfloat16 hi = __float2bfloat16(v);
    __nv_bfloat16 lo = __float2bfloat16(v - __bfloat162float(hi));
    size_t base = ((size_t)p * CIN + n) * K2;
    g_w2t[base + k]       = hi;
    g_w2t[base + 256 + k] = lo;
}

// ---------------- K1: HMMA bf16 split GEMM, cp.async double-buffered ----------------
#define BKK 64
#define ASTR 72                         // bf16 units; 144 B row stride
#define SZA (128 * ASTR * 2)            // 18432 B per tile
#define BUFB (2 * SZA)                  // A + B per buffer
#define SMTOT (2 * BUFB)                // 73728 B

__device__ __forceinline__ void mma_bf16(float* c, const uint32_t* a, const uint32_t* b) {
    asm volatile("mma.sync.aligned.m16n8k16.row.col.f32.bf16.bf16.f32 "
        "{%0,%1,%2,%3}, {%4,%5,%6,%7}, {%8,%9}, {%0,%1,%2,%3};"
        : "+f"(c[0]), "+f"(c[1]), "+f"(c[2]), "+f"(c[3])
        : "r"(a[0]), "r"(a[1]), "r"(a[2]), "r"(a[3]), "r"(b[0]), "r"(b[1]));
}
__device__ __forceinline__ void cp16(uint32_t dst, const void* src, bool valid) {
    int sz = valid ? 16 : 0;
    asm volatile("cp.async.cg.shared.global [%0], [%1], 16, %2;"
                 :: "r"(dst), "l"(src), "r"(sz));
}
__device__ __forceinline__ uint32_t cvta_s(const void* p) {
    uint32_t a;
    asm("{ .reg .u64 t; cvta.to.shared.u64 t, %1; cvt.u32.u64 %0, t; }" : "=r"(a) : "l"(p));
    return a;
}

__global__ void __launch_bounds__(256) k_mma(
    const float* __restrict__ al, const float* __restrict__ ar_) {
    extern __shared__ __align__(16) char dsm[];
    uint32_t sm0 = cvta_s(dsm);

    int p = blockIdx.z;
    int m0 = blockIdx.y * 128, n0 = blockIdx.x * 128;
    int tid = threadIdx.x, wid = tid >> 5, lane = tid & 31;
    int wm = wid & 3, wn = wid >> 2;
    int grp = lane >> 2, tg = lane & 3;

    float acc[2][8][4];
    #pragma unroll
    for (int ms = 0; ms < 2; ms++)
        #pragma unroll
        for (int nt = 0; nt < 8; nt++)
            #pragma unroll
            for (int q = 0; q < 4; q++) acc[ms][nt][q] = 0.f;

    auto load_tile = [&](int kb, int buf) {
        uint32_t base = sm0 + buf * BUFB;
        #pragma unroll
        for (int t = 0; t < 4; t++) {
            int c = tid + t * 256;
            int row = c >> 3, seg = c & 7;
            int gm = m0 + row;
            cp16(base + row * 144 + seg * 16,
                 g_h2 + (size_t)gm * K2 + kb * BKK + seg * 8, gm < NN);
            cp16(base + SZA + row * 144 + seg * 16,
                 g_w2t + ((size_t)p * CIN + n0 + row) * K2 + kb * BKK + seg * 8, true);
        }
    };

    load_tile(0, 0);
    asm volatile("cp.async.commit_group;");

    for (int kb = 0; kb < K2 / BKK; kb++) {
        if (kb + 1 < K2 / BKK) load_tile(kb + 1, (kb + 1) & 1);
        asm volatile("cp.async.commit_group;");
        asm volatile("cp.async.wait_group 1;");
        __syncthreads();

        const __nv_bfloat16* sA = (const __nv_bfloat16*)(dsm + (kb & 1) * BUFB);
        const __nv_bfloat16* sB = (const __nv_bfloat16*)(dsm + (kb & 1) * BUFB + SZA);

        #pragma unroll
        for (int ks = 0; ks < BKK / 16; ks++) {
            int k0 = ks * 16;
            uint32_t afr[2][4];
            #pragma unroll
            for (int ms = 0; ms < 2; ms++) {
                int r = wm * 32 + ms * 16;
                afr[ms][0] = *(const uint32_t*)(sA + (r + grp)     * ASTR + k0 + tg * 2);
                afr[ms][1] = *(const uint32_t*)(sA + (r + grp + 8) * ASTR + k0 + tg * 2);
                afr[ms][2] = *(const uint32_t*)(sA + (r + grp)     * ASTR + k0 + tg * 2 + 8);
                afr[ms][3] = *(const uint32_t*)(sA + (r + grp + 8) * ASTR + k0 + tg * 2 + 8);
            }
            uint32_t bfr[8][2];
            #pragma unroll
            for (int nt = 0; nt < 8; nt++) {
                int nr = wn * 64 + nt * 8 + grp;
                bfr[nt][0] = *(const uint32_t*)(sB + nr * ASTR + k0 + tg * 2);
                bfr[nt][1] = *(const uint32_t*)(sB + nr * ASTR + k0 + tg * 2 + 8);
            }
            #pragma unroll
            for (int ms = 0; ms < 2; ms++)
                #pragma unroll
                for (int nt = 0; nt < 8; nt++)
                    mma_bf16(acc[ms][nt], afr[ms], bfr[nt]);
        }
        __syncthreads();
    }

    // epilogue: store fp16 feat + fused el/er (warp tile spans exactly one head)
    int head = (n0 >> 6) + wn;
    float alv[16], arv[16];
    #pragma unroll
    for (int nt = 0; nt < 8; nt++) {
        int d = nt * 8 + tg * 2;
        alv[nt*2+0] = al [(size_t)p * CIN + head * DD + d];
        alv[nt*2+1] = al [(size_t)p * CIN + head * DD + d + 1];
        arv[nt*2+0] = ar_[(size_t)p * CIN + head * DD + d];
        arv[nt*2+1] = ar_[(size_t)p * CIN + head * DD + d + 1];
    }
    #pragma unroll
    for (int ms = 0; ms < 2; ms++) {
        int r0 = m0 + wm * 32 + ms * 16 + grp;
        int r1 = r0 + 8;
        float el0 = 0.f, er0 = 0.f, el1 = 0.f, er1 = 0.f;
        #pragma unroll
        for (int nt = 0; nt < 8; nt++) {
            float c0 = acc[ms][nt][0], c1 = acc[ms][nt][1];
            float c2 = acc[ms][nt][2], c3 = acc[ms][nt][3];
            el0 += c0 * alv[nt*2] + c1 * alv[nt*2+1];
            er0 += c0 * arv[nt*2] + c1 * arv[nt*2+1];
            el1 += c2 * alv[nt*2] + c3 * alv[nt*2+1];
            er1 += c2 * arv[nt*2] + c3 * arv[nt*2+1];
            int col = n0 + wn * 64 + nt * 8 + tg * 2;
            if (r0 < NN)
                *(__half2*)(g_f16 + ((size_t)p * NN + r0) * CIN + col) = __floats2half2_rn(c0, c1);
            if (r1 < NN)
                *(__half2*)(g_f16 + ((size_t)p * NN + r1) * CIN + col) = __floats2half2_rn(c2, c3);
        }
        #pragma unroll
        for (int off = 1; off < 4; off <<= 1) {
            el0 += __shfl_xor_sync(0xffffffffu, el0, off);
            er0 += __shfl_xor_sync(0xffffffffu, er0, off);
            el1 += __shfl_xor_sync(0xffffffffu, el1, off);
            er1 += __shfl_xor_sync(0xffffffffu, er1, off);
        }
        if (tg == 0) {
            if (r0 < NN) {
                g_el[((size_t)p * NN + r0) * HH + head] = el0;
                g_er[((size_t)p * NN + r0) * HH + head] = er0;
            }
            if (r1 < NN) {
                g_el[((size_t)p * NN + r1) * HH + head] = el1;
                g_er[((size_t)p * NN + r1) * HH + head] = er1;
            }
        }
    }
}

// ---------------- CSR build ----------------
__global__ void k_hist(const int* __restrict__ dst) {
    int e = blockIdx.x * blockDim.x + threadIdx.x;
    int p = blockIdx.z;
    if (e < EE) atomicAdd(&g_deg[p * NN + dst[(size_t)p * EE + e]], 1);
}

__device__ __forceinline__ int warp_incl_scan(int v, int lane) {
    #pragma unroll
    for (int off = 1; off < 32; off <<= 1) {
        int t = __shfl_up_sync(0xffffffffu, v, off);
        if (lane >= off) v += t;
    }
    return v;
}

__global__ void k_scanA() {
    int p = blockIdx.z, b = blockIdx.x, tid = threadIdx.x;
    int lane = tid & 31, wid = tid >> 5;
    __shared__ int ws[32];
    int idx = b * 1024 + tid;
    int v = (idx < NN) ? g_deg[p * NN + idx] : 0;
    #pragma unroll
    for (int off = 16; off; off >>= 1) v += __shfl_xor_sync(0xffffffffu, v, off);
    if (lane == 0) ws[wid] = v;
    __syncthreads();
    if (wid == 0) {
        int s = ws[lane];
        #pragma unroll
        for (int off = 16; off; off >>= 1) s += __shfl_xor_sync(0xffffffffu, s, off);
        if (lane == 0) g_bsum[p * 64 + b] = s;
    }
}
__global__ void k_scanB() {
    int p = blockIdx.z, tid = threadIdx.x;   // 64 threads
    int lane = tid & 31, w = tid >> 5;
    __shared__ int t0;
    int v = (tid < 49) ? g_bsum[p * 64 + tid] : 0;
    int sc = warp_incl_scan(v, lane);
    if (w == 0 && lane == 31) t0 = sc;
    __syncthreads();
    int incl = sc + (w == 1 ? t0 : 0);
    g_boff[p * 64 + tid] = incl - v;
}
__global__ void k_scanC() {
    int p = blockIdx.z, b = blockIdx.x, tid = threadIdx.x;
    int lane = tid & 31, wid = tid >> 5;
    __shared__ int ws[32];
    int idx = b * 1024 + tid;
    int v = (idx < NN) ? g_deg[p * NN + idx] : 0;
    int sc = warp_incl_scan(v, lane);
    if (lane == 31) ws[wid] = sc;
    __syncthreads();
    if (wid == 0) ws[lane] = warp_incl_scan(ws[lane], lane);
    __syncthreads();
    int incl = sc + (wid > 0 ? ws[wid - 1] : 0) + g_boff[p * 64 + b];
    if (idx < NN) {
        g_rowptr[p * (NN + 1) + idx + 1] = incl;
        g_cur[p * NN + idx] = incl - v;
    }
    if (b == 0 && tid == 0) g_rowptr[p * (NN + 1)] = 0;
}

__global__ void k_fill(const int* __restrict__ dst, const int* __restrict__ src) {
    int e = blockIdx.x * blockDim.x + threadIdx.x;
    int p = blockIdx.z;
    if (e >= EE) return;
    int d = dst[(size_t)p * EE + e];
    int pos = atomicAdd(&g_cur[p * NN + d], 1);
    g_eidx[(size_t)p * EE + pos] = e;
    g_esrc[(size_t)p * EE + pos] = src[(size_t)p * EE + e];
}

// ---------------- K5: fused GAT per dst node (warp per node) + BN stats ----------------
__device__ __forceinline__ float lrelu(float v) { return v > 0.f ? v : SLOPE * v; }
#define ONLINE_UPD(v, m, d) \
    do { if ((v) > (m)) { (d) = (d) * __expf((m) - (v)) + 1.f; (m) = (v); } \
         else (d) += __expf((v) - (m)); } while (0)

__global__ void __launch_bounds__(256) k_gat(
    int p, const float* __restrict__ h, float* __restrict__ attn_out) {
    __shared__ float s_sum[CIN], s_sq[CIN];
    __shared__ float s_alpha[8][4][32];
    int tid = threadIdx.x;
    s_sum[tid] = 0.f; s_sq[tid] = 0.f;
    __syncthreads();

    int gw = (blockIdx.x * blockDim.x + tid) >> 5;
    int lane = tid & 31, wid = tid >> 5;
    int n = gw;
    int beg = g_rowptr[p * (NN + 1) + n];
    int end = g_rowptr[p * (NN + 1) + n + 1];

    float acc[8];
    #pragma unroll
    for (int q = 0; q < 8; q++) acc[q] = 0.f;
    int myhead = lane >> 3;                   // channels lane*8..+8 all in head lane>>3

    if (end > beg) {
        float4 er4 = *(const float4*)(g_er + ((size_t)p * NN + n) * HH);

        // pass A: online softmax (max + denom in one traversal)
        float m0 = -1e30f, m1 = -1e30f, m2 = -1e30f, m3 = -1e30f;
        float d0 = 0.f, d1 = 0.f, d2 = 0.f, d3 = 0.f;
        for (int j = beg + lane; j < end; j += 32) {
            int s = g_esrc[(size_t)p * EE + j];
            float4 el4 = *(const float4*)(g_el + ((size_t)p * NN + s) * HH);
            float v0 = lrelu(el4.x + er4.x), v1 = lrelu(el4.y + er4.y);
            float v2 = lrelu(el4.z + er4.z), v3 = lrelu(el4.w + er4.w);
            ONLINE_UPD(v0, m0, d0); ONLINE_UPD(v1, m1, d1);
            ONLINE_UPD(v2, m2, d2); ONLINE_UPD(v3, m3, d3);
        }
        float M0 = m0, M1 = m1, M2 = m2, M3 = m3;
        #pragma unroll
        for (int off = 16; off; off >>= 1) {
            M0 = fmaxf(M0, __shfl_xor_sync(0xffffffffu, M0, off));
            M1 = fmaxf(M1, __shfl_xor_sync(0xffffffffu, M1, off));
            M2 = fmaxf(M2, __shfl_xor_sync(0xffffffffu, M2, off));
            M3 = fmaxf(M3, __shfl_xor_sync(0xffffffffu, M3, off));
        }
        d0 *= __expf(m0 - M0); d1 *= __expf(m1 - M1);
        d2 *= __expf(m2 - M2); d3 *= __expf(m3 - M3);
        #pragma unroll
        for (int off = 16; off; off >>= 1) {
            d0 += __shfl_xor_sync(0xffffffffu, d0, off);
            d1 += __shfl_xor_sync(0xffffffffu, d1, off);
            d2 += __shfl_xor_sync(0xffffffffu, d2, off);
            d3 += __shfl_xor_sync(0xffffffffu, d3, off);
        }
        float i0 = d0 > 0.f ? 1.f / d0 : 0.f;
        float i1 = d1 > 0.f ? 1.f / d1 : 0.f;
        float i2 = d2 > 0.f ? 1.f / d2 : 0.f;
        float i3 = d3 > 0.f ? 1.f / d3 : 0.f;

        // pass B: alpha (to smem) + fp16 feat gather (1 uint4/lane/edge)
        for (int jb = beg; jb < end; jb += 32) {
            int j = jb + lane;
            int sj = 0;
            if (j < end) {
                int eid = g_eidx[(size_t)p * EE + j];
                sj = g_esrc[(size_t)p * EE + j];
                float4 el4 = *(const float4*)(g_el + ((size_t)p * NN + sj) * HH);
                float a0 = __expf(lrelu(el4.x + er4.x) - M0) * i0;
                float a1 = __expf(lrelu(el4.y + er4.y) - M1) * i1;
                float a2 = __expf(lrelu(el4.z + er4.z) - M2) * i2;
                float a3 = __expf(lrelu(el4.w + er4.w) - M3) * i3;
                s_alpha[wid][0][lane] = a0; s_alpha[wid][1][lane] = a1;
                s_alpha[wid][2][lane] = a2; s_alpha[wid][3][lane] = a3;
                attn_out[(size_t)p * EE + eid] = 0.25f * (a0 + a1 + a2 + a3);
            }
            __syncwarp();
            int cnt = min(32, end - jb);
            for (int t = 0; t < cnt; t++) {
                int s_t = __shfl_sync(0xffffffffu, sj, t);
                float w = s_alpha[wid][myhead][t];
                const uint4* fp = (const uint4*)(g_f16 + ((size_t)p * NN + s_t) * CIN);
                uint4 qv = fp[lane];                       // 8 halves = channels lane*8..+8
                const __half2* hh = (const __half2*)&qv;
                float2 u0 = __half22float2(hh[0]);
                float2 u1 = __half22float2(hh[1]);
                float2 u2 = __half22float2(hh[2]);
                float2 u3 = __half22float2(hh[3]);
                acc[0] += u0.x * w; acc[1] += u0.y * w;
                acc[2] += u1.x * w; acc[3] += u1.y * w;
                acc[4] += u2.x * w; acc[5] += u2.y * w;
                acc[6] += u3.x * w; acc[7] += u3.y * w;
            }
            __syncwarp();
        }
    }

    // epilogue: x = relu(out) + h over channels lane*8..+8
    int cb = lane * 8;
    float4 h0 = *(const float4*)(h + (size_t)n * CIN + cb);
    float4 h1 = *(const float4*)(h + (size_t)n * CIN + cb + 4);
    float x[8];
    x[0] = fmaxf(acc[0], 0.f) + h0.x; x[1] = fmaxf(acc[1], 0.f) + h0.y;
    x[2] = fmaxf(acc[2], 0.f) + h0.z; x[3] = fmaxf(acc[3], 0.f) + h0.w;
    x[4] = fmaxf(acc[4], 0.f) + h1.x; x[5] = fmaxf(acc[5], 0.f) + h1.y;
    x[6] = fmaxf(acc[6], 0.f) + h1.z; x[7] = fmaxf(acc[7], 0.f) + h1.w;
    float* op = g_accum + ((size_t)p * NN + n) * CIN + cb;
    *(float4*)(op)     = make_float4(x[0], x[1], x[2], x[3]);
    *(float4*)(op + 4) = make_float4(x[4], x[5], x[6], x[7]);

    #pragma unroll
    for (int q = 0; q < 8; q++) {
        atomicAdd(&s_sum[cb + q], x[q]);
        atomicAdd(&s_sq[cb + q],  x[q] * x[q]);
    }
    __syncthreads();
    atomicAdd(&g_sum[p * CIN + tid], s_sum[tid]);
    atomicAdd(&g_sumsq[p * CIN + tid], s_sq[tid]);
}

// ---------------- K7: BN affine ----------------
__global__ void k_bnfin(const float* __restrict__ gamma, const float* __restrict__ beta) {
    int p = blockIdx.z; int c = threadIdx.x;
    float mu  = g_sum[p * CIN + c] * (1.f / NN);
    float var = g_sumsq[p * CIN + c] * (1.f / NN) - mu * mu;
    float sc = gamma[c] * rsqrtf(var + EPS);
    g_scale[p * CIN + c] = sc;
    g_shift[p * CIN + c] = beta[c] - sc * mu;
}

// ---------------- K8: pooled output ----------------
__global__ void k_pool(const float* __restrict__ wmat, float* __restrict__ pooled) {
    int idx = blockIdx.x * blockDim.x + threadIdx.x;
    if (idx >= NN * 64) return;
    int n = idx >> 6, c4 = (idx & 63) * 4;
    float4 acc = make_float4(0.f, 0.f, 0.f, 0.f);
    #pragma unroll
    for (int p = 0; p < PP; p++) {
        float wv = wmat[n * PP + p];
        float4 x  = *(const float4*)(g_accum + ((size_t)p * NN + n) * CIN + c4);
        float4 sc = *(const float4*)(g_scale + p * CIN + c4);
        float4 sh = *(const float4*)(g_shift + p * CIN + c4);
        acc.x += wv * (sc.x * x.x + sh.x);
        acc.y += wv * (sc.y * x.y + sh.y);
        acc.z += wv * (sc.z * x.z + sh.z);
        acc.w += wv * (sc.w * x.w + sh.w);
    }
    *(float4*)(pooled + (size_t)n * CIN + c4) = acc;
}

// ---------------- host ----------------
extern "C" void kernel_launch(void* const* d_in, const int* in_sizes, int n_in,
                              void* d_out, int out_size) {
    const float* h     = (const float*)d_in[0];
    const float* mask  = (const float*)d_in[1];
    const int*   src   = (const int*)  d_in[2];
    const int*   dst   = (const int*)  d_in[3];
    const float* fc    = (const float*)d_in[4];
    const float* al    = (const float*)d_in[5];
    const float* ar    = (const float*)d_in[6];
    const float* gamma = (const float*)d_in[7];
    const float* beta  = (const float*)d_in[8];

    float* out    = (float*)d_out;
    float* pooled = out;
    float* wout   = out + (size_t)NN * CIN;
    float* attn   = wout + (size_t)NN * PP;

    cudaFuncSetAttribute(k_mma, cudaFuncAttributeMaxDynamicSharedMemorySize, SMTOT);

    k_zero<<<(PP * NN + 255) / 256, 256>>>();
    k_cvt_h<<<(int)(((size_t)NN * CIN + 255) / 256), 256>>>(h);
    k_cvt_w<<<(PP * CIN * CIN + 255) / 256, 256>>>(fc);

    dim3 gm(CIN / 128, (NN + 127) / 128, PP);
    k_mma<<<gm, 256, SMTOT>>>(al, ar);

    k_w<<<(NN + 255) / 256, 256>>>(mask, wout);

    k_hist<<<dim3((EE + 255) / 256, 1, PP), 256>>>(dst);
    k_scanA<<<dim3(49, 1, PP), 1024>>>();
    k_scanB<<<dim3(1, 1, PP), 64>>>();
    k_scanC<<<dim3(49, 1, PP), 1024>>>();
    k_fill<<<dim3((EE + 255) / 256, 1, PP), 256>>>(dst, src);

    for (int p = 0; p < PP; p++)
        k_gat<<<(NN * 32) / 256, 256>>>(p, h, attn);

    k_bnfin<<<dim3(1, 1, PP), 256>>>(gamma, beta);
    k_pool<<<(NN * 64 + 255) / 256, 256>>>(wout, pooled);
}

// round 9
// speedup vs baseline: 1.3380x; 1.3380x over previous
#include <cuda_runtime.h>
#include <cuda_bf16.h>
#include <cuda_fp16.h>
#include <cstdint>

#define NN   50000
#define EE   800000
#define PP   3
#define HH   4
#define DD   64
#define CIN  256          // H*D = in_size
#define K2   512          // split-K (hi|lo concat)
#define EPS  1e-5f
#define SLOPE 0.2f

// ---------------- device scratch (static, no allocation) ----------------
__device__ __align__(256) __half g_f16 [(size_t)PP*NN*CIN];   // fp16 projected features
__device__ __align__(256) float g_accum[(size_t)PP*NN*CIN];
__device__ __align__(256) __nv_bfloat16 g_h2 [(size_t)NN*K2];
__device__ __align__(256) __nv_bfloat16 g_w2t[(size_t)PP*CIN*K2];
__device__ __align__(16)  float g_el   [PP*NN*HH];
__device__ __align__(16)  float g_er   [PP*NN*HH];
__device__ int g_deg   [PP*NN];
__device__ int g_rowptr[PP*(NN+1)];
__device__ int g_cur   [PP*NN];
__device__ int g_bsum  [PP*64];
__device__ int g_boff  [PP*64];
__device__ int g_eidx  [(size_t)PP*EE];
__device__ int g_esrc  [(size_t)PP*EE];
__device__ float g_sum  [PP*CIN];
__device__ float g_sumsq[PP*CIN];
__device__ float g_scale[PP*CIN];
__device__ float g_shift[PP*CIN];

// ---------------- K0: zero small scratch ----------------
__global__ void k_zero() {
    int i = blockIdx.x * blockDim.x + threadIdx.x;
    if (i < PP * NN) g_deg[i] = 0;
    if (i < PP * CIN) { g_sum[i] = 0.f; g_sumsq[i] = 0.f; }
}

// ---------------- Kw: semantic weights ----------------
__global__ void k_w(const float* __restrict__ mask, float* __restrict__ wout) {
    int n = blockIdx.x * blockDim.x + threadIdx.x;
    if (n >= NN) return;
    float m0 = mask[n*PP+0], m1 = mask[n*PP+1], m2 = mask[n*PP+2];
    float inv = 1.f / (m0 + m1 + m2);
    wout[n*PP+0] = m0 * inv;
    wout[n*PP+1] = m1 * inv;
    wout[n*PP+2] = m2 * inv;
}

// ---------------- conversions: fp32 -> bf16 hi/lo split ----------------
__global__ void k_cvt_h(const float* __restrict__ h) {
    size_t i = (size_t)blockIdx.x * blockDim.x + threadIdx.x;
    if (i >= (size_t)NN * CIN) return;
    size_t m = i >> 8, k = i & 255;
    float v = h[i];
    __nv_bfloat16 hi = __float2bfloat16(v);
    __nv_bfloat16 lo = __float2bfloat16(v - __bfloat162float(hi));
    g_h2[m * K2 + k]       = hi;
    g_h2[m * K2 + 256 + k] = lo;
}
__global__ void k_cvt_w(const float* __restrict__ fc) {
    int i = blockIdx.x * blockDim.x + threadIdx.x;
    if (i >= PP * CIN * CIN) return;
    int p = i >> 16, rem = i & 65535;
    int k = rem >> 8, n = rem & 255;
    float v = fc[i];
    __nv_bfloat16 hi = __float2bfloat16(v);
    __nv_bfloat16 lo = __float2bfloat16(v - __bfloat162float(hi));
    size_t base = ((size_t)p * CIN + n) * K2;
    g_w2t[base + k]       = hi;
    g_w2t[base + 256 + k] = lo;
}

// ---------------- K1: HMMA bf16 split GEMM, cp.async double-buffered ----------------
#define BKK 64
#define ASTR 72                         // bf16 units; 144 B row stride
#define SZA (128 * ASTR * 2)            // 18432 B per tile
#define BUFB (2 * SZA)                  // A + B per buffer
#define SMTOT (2 * BUFB)                // 73728 B

__device__ __forceinline__ void mma_bf16(float* c, const uint32_t* a, const uint32_t* b) {
    asm volatile("mma.sync.aligned.m16n8k16.row.col.f32.bf16.bf16.f32 "
        "{%0,%1,%2,%3}, {%4,%5,%6,%7}, {%8,%9}, {%0,%1,%2,%3};"
        : "+f"(c[0]), "+f"(c[1]), "+f"(c[2]), "+f"(c[3])
        : "r"(a[0]), "r"(a[1]), "r"(a[2]), "r"(a[3]), "r"(b[0]), "r"(b[1]));
}
__device__ __forceinline__ void cp16(uint32_t dst, const void* src, bool valid) {
    int sz = valid ? 16 : 0;
    asm volatile("cp.async.cg.shared.global [%0], [%1], 16, %2;"
                 :: "r"(dst), "l"(src), "r"(sz));
}
__device__ __forceinline__ uint32_t cvta_s(const void* p) {
    uint32_t a;
    asm("{ .reg .u64 t; cvta.to.shared.u64 t, %1; cvt.u32.u64 %0, t; }" : "=r"(a) : "l"(p));
    return a;
}

__global__ void __launch_bounds__(256) k_mma(
    const float* __restrict__ al, const float* __restrict__ ar_) {
    extern __shared__ __align__(16) char dsm[];
    uint32_t sm0 = cvta_s(dsm);

    int p = blockIdx.z;
    int m0 = blockIdx.y * 128, n0 = blockIdx.x * 128;
    int tid = threadIdx.x, wid = tid >> 5, lane = tid & 31;
    int wm = wid & 3, wn = wid >> 2;
    int grp = lane >> 2, tg = lane & 3;

    float acc[2][8][4];
    #pragma unroll
    for (int ms = 0; ms < 2; ms++)
        #pragma unroll
        for (int nt = 0; nt < 8; nt++)
            #pragma unroll
            for (int q = 0; q < 4; q++) acc[ms][nt][q] = 0.f;

    auto load_tile = [&](int kb, int buf) {
        uint32_t base = sm0 + buf * BUFB;
        #pragma unroll
        for (int t = 0; t < 4; t++) {
            int c = tid + t * 256;
            int row = c >> 3, seg = c & 7;
            int gm = m0 + row;
            cp16(base + row * 144 + seg * 16,
                 g_h2 + (size_t)gm * K2 + kb * BKK + seg * 8, gm < NN);
            cp16(base + SZA + row * 144 + seg * 16,
                 g_w2t + ((size_t)p * CIN + n0 + row) * K2 + kb * BKK + seg * 8, true);
        }
    };

    load_tile(0, 0);
    asm volatile("cp.async.commit_group;");

    for (int kb = 0; kb < K2 / BKK; kb++) {
        if (kb + 1 < K2 / BKK) load_tile(kb + 1, (kb + 1) & 1);
        asm volatile("cp.async.commit_group;");
        asm volatile("cp.async.wait_group 1;");
        __syncthreads();

        const __nv_bfloat16* sA = (const __nv_bfloat16*)(dsm + (kb & 1) * BUFB);
        const __nv_bfloat16* sB = (const __nv_bfloat16*)(dsm + (kb & 1) * BUFB + SZA);

        #pragma unroll
        for (int ks = 0; ks < BKK / 16; ks++) {
            int k0 = ks * 16;
            uint32_t afr[2][4];
            #pragma unroll
            for (int ms = 0; ms < 2; ms++) {
                int r = wm * 32 + ms * 16;
                afr[ms][0] = *(const uint32_t*)(sA + (r + grp)     * ASTR + k0 + tg * 2);
                afr[ms][1] = *(const uint32_t*)(sA + (r + grp + 8) * ASTR + k0 + tg * 2);
                afr[ms][2] = *(const uint32_t*)(sA + (r + grp)     * ASTR + k0 + tg * 2 + 8);
                afr[ms][3] = *(const uint32_t*)(sA + (r + grp + 8) * ASTR + k0 + tg * 2 + 8);
            }
            uint32_t bfr[8][2];
            #pragma unroll
            for (int nt = 0; nt < 8; nt++) {
                int nr = wn * 64 + nt * 8 + grp;
                bfr[nt][0] = *(const uint32_t*)(sB + nr * ASTR + k0 + tg * 2);
                bfr[nt][1] = *(const uint32_t*)(sB + nr * ASTR + k0 + tg * 2 + 8);
            }
            #pragma unroll
            for (int ms = 0; ms < 2; ms++)
                #pragma unroll
                for (int nt = 0; nt < 8; nt++)
                    mma_bf16(acc[ms][nt], afr[ms], bfr[nt]);
        }
        __syncthreads();
    }

    // epilogue: store fp16 feat + fused el/er (warp tile spans exactly one head)
    int head = (n0 >> 6) + wn;
    float alv[16], arv[16];
    #pragma unroll
    for (int nt = 0; nt < 8; nt++) {
        int d = nt * 8 + tg * 2;
        alv[nt*2+0] = al [(size_t)p * CIN + head * DD + d];
        alv[nt*2+1] = al [(size_t)p * CIN + head * DD + d + 1];
        arv[nt*2+0] = ar_[(size_t)p * CIN + head * DD + d];
        arv[nt*2+1] = ar_[(size_t)p * CIN + head * DD + d + 1];
    }
    #pragma unroll
    for (int ms = 0; ms < 2; ms++) {
        int r0 = m0 + wm * 32 + ms * 16 + grp;
        int r1 = r0 + 8;
        float el0 = 0.f, er0 = 0.f, el1 = 0.f, er1 = 0.f;
        #pragma unroll
        for (int nt = 0; nt < 8; nt++) {
            float c0 = acc[ms][nt][0], c1 = acc[ms][nt][1];
            float c2 = acc[ms][nt][2], c3 = acc[ms][nt][3];
            el0 += c0 * alv[nt*2] + c1 * alv[nt*2+1];
            er0 += c0 * arv[nt*2] + c1 * arv[nt*2+1];
            el1 += c2 * alv[nt*2] + c3 * alv[nt*2+1];
            er1 += c2 * arv[nt*2] + c3 * arv[nt*2+1];
            int col = n0 + wn * 64 + nt * 8 + tg * 2;
            if (r0 < NN)
                *(__half2*)(g_f16 + ((size_t)p * NN + r0) * CIN + col) = __floats2half2_rn(c0, c1);
            if (r1 < NN)
                *(__half2*)(g_f16 + ((size_t)p * NN + r1) * CIN + col) = __floats2half2_rn(c2, c3);
        }
        #pragma unroll
        for (int off = 1; off < 4; off <<= 1) {
            el0 += __shfl_xor_sync(0xffffffffu, el0, off);
            er0 += __shfl_xor_sync(0xffffffffu, er0, off);
            el1 += __shfl_xor_sync(0xffffffffu, el1, off);
            er1 += __shfl_xor_sync(0xffffffffu, er1, off);
        }
        if (tg == 0) {
            if (r0 < NN) {
                g_el[((size_t)p * NN + r0) * HH + head] = el0;
                g_er[((size_t)p * NN + r0) * HH + head] = er0;
            }
            if (r1 < NN) {
                g_el[((size_t)p * NN + r1) * HH + head] = el1;
                g_er[((size_t)p * NN + r1) * HH + head] = er1;
            }
        }
    }
}

// ---------------- CSR build ----------------
__global__ void k_hist(const int* __restrict__ dst) {
    int e = blockIdx.x * blockDim.x + threadIdx.x;
    int p = blockIdx.z;
    if (e < EE) atomicAdd(&g_deg[p * NN + dst[(size_t)p * EE + e]], 1);
}

__device__ __forceinline__ int warp_incl_scan(int v, int lane) {
    #pragma unroll
    for (int off = 1; off < 32; off <<= 1) {
        int t = __shfl_up_sync(0xffffffffu, v, off);
        if (lane >= off) v += t;
    }
    return v;
}

__global__ void k_scanA() {
    int p = blockIdx.z, b = blockIdx.x, tid = threadIdx.x;
    int lane = tid & 31, wid = tid >> 5;
    __shared__ int ws[32];
    int idx = b * 1024 + tid;
    int v = (idx < NN) ? g_deg[p * NN + idx] : 0;
    #pragma unroll
    for (int off = 16; off; off >>= 1) v += __shfl_xor_sync(0xffffffffu, v, off);
    if (lane == 0) ws[wid] = v;
    __syncthreads();
    if (wid == 0) {
        int s = ws[lane];
        #pragma unroll
        for (int off = 16; off; off >>= 1) s += __shfl_xor_sync(0xffffffffu, s, off);
        if (lane == 0) g_bsum[p * 64 + b] = s;
    }
}
__global__ void k_scanB() {
    int p = blockIdx.z, tid = threadIdx.x;   // 64 threads
    int lane = tid & 31, w = tid >> 5;
    __shared__ int t0;
    int v = (tid < 49) ? g_bsum[p * 64 + tid] : 0;
    int sc = warp_incl_scan(v, lane);
    if (w == 0 && lane == 31) t0 = sc;
    __syncthreads();
    int incl = sc + (w == 1 ? t0 : 0);
    g_boff[p * 64 + tid] = incl - v;
}
__global__ void k_scanC() {
    int p = blockIdx.z, b = blockIdx.x, tid = threadIdx.x;
    int lane = tid & 31, wid = tid >> 5;
    __shared__ int ws[32];
    int idx = b * 1024 + tid;
    int v = (idx < NN) ? g_deg[p * NN + idx] : 0;
    int sc = warp_incl_scan(v, lane);
    if (lane == 31) ws[wid] = sc;
    __syncthreads();
    if (wid == 0) ws[lane] = warp_incl_scan(ws[lane], lane);
    __syncthreads();
    int incl = sc + (wid > 0 ? ws[wid - 1] : 0) + g_boff[p * 64 + b];
    if (idx < NN) {
        g_rowptr[p * (NN + 1) + idx + 1] = incl;
        g_cur[p * NN + idx] = incl - v;
    }
    if (b == 0 && tid == 0) g_rowptr[p * (NN + 1)] = 0;
}

__global__ void k_fill(const int* __restrict__ dst, const int* __restrict__ src) {
    int e = blockIdx.x * blockDim.x + threadIdx.x;
    int p = blockIdx.z;
    if (e >= EE) return;
    int d = dst[(size_t)p * EE + e];
    int pos = atomicAdd(&g_cur[p * NN + d], 1);
    g_eidx[(size_t)p * EE + pos] = e;
    g_esrc[(size_t)p * EE + pos] = src[(size_t)p * EE + e];
}

// ---------------- K5: fused GAT per dst node (warp per node) + BN stats ----------------
__device__ __forceinline__ float lrelu(float v) { return v > 0.f ? v : SLOPE * v; }
#define ONLINE_UPD(v, m, d) \
    do { if ((v) > (m)) { (d) = (d) * __expf((m) - (v)) + 1.f; (m) = (v); } \
         else (d) += __expf((v) - (m)); } while (0)
#define CAP 64

__global__ void __launch_bounds__(256) k_gat(
    int p, const float* __restrict__ h, float* __restrict__ attn_out) {
    __shared__ float s_v  [8][CAP][4];   // cached leaky-relu scores (pass A -> pass B)
    __shared__ int   s_src[8][CAP];      // cached src ids
    __shared__ float s_a  [8][32][4];    // per-block alphas
    __shared__ float s_x  [8][CIN];      // BN transpose-reduce buffer

    int tid = threadIdx.x;
    int lane = tid & 31, wid = tid >> 5;
    int n = blockIdx.x * 8 + wid;        // NN = 6250 * 8, always < NN
    int beg = g_rowptr[p * (NN + 1) + n];
    int end = g_rowptr[p * (NN + 1) + n + 1];
    int myhead = lane >> 3;

    float acc[8];
    #pragma unroll
    for (int q = 0; q < 8; q++) acc[q] = 0.f;

    if (end > beg) {
        float4 er4 = *(const float4*)(g_er + ((size_t)p * NN + n) * HH);

        // pass A: online softmax + cache v/src in smem
        float m0 = -1e30f, m1 = -1e30f, m2 = -1e30f, m3 = -1e30f;
        float d0 = 0.f, d1 = 0.f, d2 = 0.f, d3 = 0.f;
        for (int j = beg + lane; j < end; j += 32) {
            int s = g_esrc[(size_t)p * EE + j];
            float4 el4 = *(const float4*)(g_el + ((size_t)p * NN + s) * HH);
            float v0 = lrelu(el4.x + er4.x), v1 = lrelu(el4.y + er4.y);
            float v2 = lrelu(el4.z + er4.z), v3 = lrelu(el4.w + er4.w);
            int slot = j - beg;
            if (slot < CAP) {
                s_src[wid][slot] = s;
                *(float4*)s_v[wid][slot] = make_float4(v0, v1, v2, v3);
            }
            ONLINE_UPD(v0, m0, d0); ONLINE_UPD(v1, m1, d1);
            ONLINE_UPD(v2, m2, d2); ONLINE_UPD(v3, m3, d3);
        }
        float M0 = m0, M1 = m1, M2 = m2, M3 = m3;
        #pragma unroll
        for (int off = 16; off; off >>= 1) {
            M0 = fmaxf(M0, __shfl_xor_sync(0xffffffffu, M0, off));
            M1 = fmaxf(M1, __shfl_xor_sync(0xffffffffu, M1, off));
            M2 = fmaxf(M2, __shfl_xor_sync(0xffffffffu, M2, off));
            M3 = fmaxf(M3, __shfl_xor_sync(0xffffffffu, M3, off));
        }
        d0 *= __expf(m0 - M0); d1 *= __expf(m1 - M1);
        d2 *= __expf(m2 - M2); d3 *= __expf(m3 - M3);
        #pragma unroll
        for (int off = 16; off; off >>= 1) {
            d0 += __shfl_xor_sync(0xffffffffu, d0, off);
            d1 += __shfl_xor_sync(0xffffffffu, d1, off);
            d2 += __shfl_xor_sync(0xffffffffu, d2, off);
            d3 += __shfl_xor_sync(0xffffffffu, d3, off);
        }
        float i0 = d0 > 0.f ? 1.f / d0 : 0.f;
        float i1 = d1 > 0.f ? 1.f / d1 : 0.f;
        float i2 = d2 > 0.f ? 1.f / d2 : 0.f;
        float i3 = d3 > 0.f ? 1.f / d3 : 0.f;

        // pass B blocks of 32 edges
        for (int jb = beg; jb < end; jb += 32) {
            int j = jb + lane;
            int sj = 0;
            if (j < end) {
                int slot = j - beg;
                float4 v4;
                if (slot < CAP) {
                    v4 = *(const float4*)s_v[wid][slot];
                    sj = s_src[wid][slot];
                } else {                                  // ultra-rare overflow
                    sj = g_esrc[(size_t)p * EE + j];
                    float4 el4 = *(const float4*)(g_el + ((size_t)p * NN + sj) * HH);
                    v4 = make_float4(lrelu(el4.x + er4.x), lrelu(el4.y + er4.y),
                                     lrelu(el4.z + er4.z), lrelu(el4.w + er4.w));
                }
                float a0 = __expf(v4.x - M0) * i0;
                float a1 = __expf(v4.y - M1) * i1;
                float a2 = __expf(v4.z - M2) * i2;
                float a3 = __expf(v4.w - M3) * i3;
                *(float4*)s_a[wid][lane] = make_float4(a0, a1, a2, a3);
                int eid = g_eidx[(size_t)p * EE + j];
                attn_out[(size_t)p * EE + eid] = 0.25f * (a0 + a1 + a2 + a3);
            }
            __syncwarp();
            int cnt = min(32, end - jb);
            int tb = jb - beg;
            int t = 0;
            for (; t + 1 < cnt; t += 2) {
                int t0g = tb + t, t1g = t0g + 1;
                int s0 = (t0g < CAP) ? s_src[wid][t0g] : __shfl_sync(0xffffffffu, sj, t);
                int s1 = (t1g < CAP) ? s_src[wid][t1g] : __shfl_sync(0xffffffffu, sj, t + 1);
                uint4 q0 = ((const uint4*)(g_f16 + ((size_t)p * NN + s0) * CIN))[lane];
                uint4 q1 = ((const uint4*)(g_f16 + ((size_t)p * NN + s1) * CIN))[lane];
                float w0 = s_a[wid][t][myhead];
                float w1 = s_a[wid][t + 1][myhead];
                const __half2* ha = (const __half2*)&q0;
                const __half2* hb = (const __half2*)&q1;
                #pragma unroll
                for (int q = 0; q < 4; q++) {
                    float2 ua = __half22float2(ha[q]);
                    float2 ub = __half22float2(hb[q]);
                    acc[q*2+0] += ua.x * w0 + ub.x * w1;
                    acc[q*2+1] += ua.y * w0 + ub.y * w1;
                }
            }
            if (t < cnt) {
                int t0g = tb + t;
                int s0 = (t0g < CAP) ? s_src[wid][t0g] : __shfl_sync(0xffffffffu, sj, t);
                uint4 q0 = ((const uint4*)(g_f16 + ((size_t)p * NN + s0) * CIN))[lane];
                float w0 = s_a[wid][t][myhead];
                const __half2* ha = (const __half2*)&q0;
                #pragma unroll
                for (int q = 0; q < 4; q++) {
                    float2 ua = __half22float2(ha[q]);
                    acc[q*2+0] += ua.x * w0;
                    acc[q*2+1] += ua.y * w0;
                }
            }
            __syncwarp();
        }
    }

    // epilogue: x = relu(out) + h over channels lane*8..+8
    int cb = lane * 8;
    float4 h0 = *(const float4*)(h + (size_t)n * CIN + cb);
    float4 h1 = *(const float4*)(h + (size_t)n * CIN + cb + 4);
    float x[8];
    x[0] = fmaxf(acc[0], 0.f) + h0.x; x[1] = fmaxf(acc[1], 0.f) + h0.y;
    x[2] = fmaxf(acc[2], 0.f) + h0.z; x[3] = fmaxf(acc[3], 0.f) + h0.w;
    x[4] = fmaxf(acc[4], 0.f) + h1.x; x[5] = fmaxf(acc[5], 0.f) + h1.y;
    x[6] = fmaxf(acc[6], 0.f) + h1.z; x[7] = fmaxf(acc[7], 0.f) + h1.w;
    float* op = g_accum + ((size_t)p * NN + n) * CIN + cb;
    *(float4*)(op)     = make_float4(x[0], x[1], x[2], x[3]);
    *(float4*)(op + 4) = make_float4(x[4], x[5], x[6], x[7]);

    // BN stats: transpose-reduce through smem (no atomics except 2 global per thread)
    *(float4*)&s_x[wid][cb]     = make_float4(x[0], x[1], x[2], x[3]);
    *(float4*)&s_x[wid][cb + 4] = make_float4(x[4], x[5], x[6], x[7]);
    __syncthreads();
    float ssum = 0.f, ssq = 0.f;
    #pragma unroll
    for (int w = 0; w < 8; w++) {
        float v = s_x[w][tid];
        ssum += v; ssq += v * v;
    }
    atomicAdd(&g_sum[p * CIN + tid], ssum);
    atomicAdd(&g_sumsq[p * CIN + tid], ssq);
}

// ---------------- K7: BN affine ----------------
__global__ void k_bnfin(const float* __restrict__ gamma, const float* __restrict__ beta) {
    int p = blockIdx.z; int c = threadIdx.x;
    float mu  = g_sum[p * CIN + c] * (1.f / NN);
    float var = g_sumsq[p * CIN + c] * (1.f / NN) - mu * mu;
    float sc = gamma[c] * rsqrtf(var + EPS);
    g_scale[p * CIN + c] = sc;
    g_shift[p * CIN + c] = beta[c] - sc * mu;
}

// ---------------- K8: pooled output ----------------
__global__ void k_pool(const float* __restrict__ wmat, float* __restrict__ pooled) {
    int idx = blockIdx.x * blockDim.x + threadIdx.x;
    if (idx >= NN * 64) return;
    int n = idx >> 6, c4 = (idx & 63) * 4;
    float4 acc = make_float4(0.f, 0.f, 0.f, 0.f);
    #pragma unroll
    for (int p = 0; p < PP; p++) {
        float wv = wmat[n * PP + p];
        float4 x  = *(const float4*)(g_accum + ((size_t)p * NN + n) * CIN + c4);
        float4 sc = *(const float4*)(g_scale + p * CIN + c4);
        float4 sh = *(const float4*)(g_shift + p * CIN + c4);
        acc.x += wv * (sc.x * x.x + sh.x);
        acc.y += wv * (sc.y * x.y + sh.y);
        acc.z += wv * (sc.z * x.z + sh.z);
        acc.w += wv * (sc.w * x.w + sh.w);
    }
    *(float4*)(pooled + (size_t)n * CIN + c4) = acc;
}

// ---------------- host ----------------
extern "C" void kernel_launch(void* const* d_in, const int* in_sizes, int n_in,
                              void* d_out, int out_size) {
    const float* h     = (const float*)d_in[0];
    const float* mask  = (const float*)d_in[1];
    const int*   src   = (const int*)  d_in[2];
    const int*   dst   = (const int*)  d_in[3];
    const float* fc    = (const float*)d_in[4];
    const float* al    = (const float*)d_in[5];
    const float* ar    = (const float*)d_in[6];
    const float* gamma = (const float*)d_in[7];
    const float* beta  = (const float*)d_in[8];

    float* out    = (float*)d_out;
    float* pooled = out;
    float* wout   = out + (size_t)NN * CIN;
    float* attn   = wout + (size_t)NN * PP;

    cudaFuncSetAttribute(k_mma, cudaFuncAttributeMaxDynamicSharedMemorySize, SMTOT);

    k_zero<<<(PP * NN + 255) / 256, 256>>>();
    k_cvt_h<<<(int)(((size_t)NN * CIN + 255) / 256), 256>>>(h);
    k_cvt_w<<<(PP * CIN * CIN + 255) / 256, 256>>>(fc);

    dim3 gm(CIN / 128, (NN + 127) / 128, PP);
    k_mma<<<gm, 256, SMTOT>>>(al, ar);

    k_w<<<(NN + 255) / 256, 256>>>(mask, wout);

    k_hist<<<dim3((EE + 255) / 256, 1, PP), 256>>>(dst);
    k_scanA<<<dim3(49, 1, PP), 1024>>>();
    k_scanB<<<dim3(1, 1, PP), 64>>>();
    k_scanC<<<dim3(49, 1, PP), 1024>>>();
    k_fill<<<dim3((EE + 255) / 256, 1, PP), 256>>>(dst, src);

    for (int p = 0; p < PP; p++)
        k_gat<<<NN / 8, 256>>>(p, h, attn);

    k_bnfin<<<dim3(1, 1, PP), 256>>>(gamma, beta);
    k_pool<<<(NN * 64 + 255) / 256, 256>>>(wout, pooled);
}

// round 13
// speedup vs baseline: 1.5190x; 1.1353x over previous
#include <cuda_runtime.h>
#include <cuda_bf16.h>
#include <cuda_fp16.h>
#include <cstdint>

#define NN   50000
#define EE   800000
#define PP   3
#define HH   4
#define DD   64
#define CIN  256          // H*D = in_size
#define K2   256          // GEMM K (bf16 hi only; lo terms negligible)
#define EPS  1e-5f
#define SLOPE 0.2f

// ---------------- device scratch (static, no allocation) ----------------
__device__ __align__(256) __half g_f16 [(size_t)PP*NN*CIN];   // fp16 projected features
__device__ __align__(256) float g_accum[(size_t)PP*NN*CIN];
__device__ __align__(256) __nv_bfloat16 g_h2 [(size_t)NN*K2];
__device__ __align__(256) __nv_bfloat16 g_w2t[(size_t)PP*CIN*K2];
__device__ __align__(16)  float g_el   [PP*NN*HH];
__device__ __align__(16)  float g_er   [PP*NN*HH];
__device__ int g_deg   [PP*NN];
__device__ int g_rowptr[PP*(NN+1)];
__device__ int g_cur   [PP*NN];
__device__ int g_bsum  [PP*64];
__device__ int g_boff  [PP*64];
__device__ int g_eidx  [(size_t)PP*EE];
__device__ int g_esrc  [(size_t)PP*EE];
__device__ float g_sum  [PP*CIN];
__device__ float g_sumsq[PP*CIN];
__device__ float g_scale[PP*CIN];
__device__ float g_shift[PP*CIN];

// ---------------- K0: zero small scratch ----------------
__global__ void k_zero() {
    int i = blockIdx.x * blockDim.x + threadIdx.x;
    if (i < PP * NN) g_deg[i] = 0;
    if (i < PP * CIN) { g_sum[i] = 0.f; g_sumsq[i] = 0.f; }
}

// ---------------- Kw: semantic weights ----------------
__global__ void k_w(const float* __restrict__ mask, float* __restrict__ wout) {
    int n = blockIdx.x * blockDim.x + threadIdx.x;
    if (n >= NN) return;
    float m0 = mask[n*PP+0], m1 = mask[n*PP+1], m2 = mask[n*PP+2];
    float inv = 1.f / (m0 + m1 + m2);
    wout[n*PP+0] = m0 * inv;
    wout[n*PP+1] = m1 * inv;
    wout[n*PP+2] = m2 * inv;
}

// ---------------- conversions: fp32 -> bf16 ----------------
__global__ void k_cvt_h(const float* __restrict__ h) {
    size_t i = (size_t)blockIdx.x * blockDim.x + threadIdx.x;
    if (i >= (size_t)NN * CIN) return;
    g_h2[i] = __float2bfloat16(h[i]);
}
__global__ void k_cvt_w(const float* __restrict__ fc) {
    int i = blockIdx.x * blockDim.x + threadIdx.x;
    if (i >= PP * CIN * CIN) return;
    int p = i >> 16, rem = i & 65535;
    int k = rem >> 8, n = rem & 255;
    g_w2t[((size_t)p * CIN + n) * K2 + k] = __float2bfloat16(fc[i]);
}

// ---------------- K1: HMMA bf16 GEMM, cp.async double-buffered ----------------
#define BKK 64
#define ASTR 72                         // bf16 units; 144 B row stride
#define SZA (128 * ASTR * 2)            // 18432 B per tile
#define BUFB (2 * SZA)                  // A + B per buffer
#define SMTOT (2 * BUFB)                // 73728 B

__device__ __forceinline__ void mma_bf16(float* c, const uint32_t* a, const uint32_t* b) {
    asm volatile("mma.sync.aligned.m16n8k16.row.col.f32.bf16.bf16.f32 "
        "{%0,%1,%2,%3}, {%4,%5,%6,%7}, {%8,%9}, {%0,%1,%2,%3};"
        : "+f"(c[0]), "+f"(c[1]), "+f"(c[2]), "+f"(c[3])
        : "r"(a[0]), "r"(a[1]), "r"(a[2]), "r"(a[3]), "r"(b[0]), "r"(b[1]));
}
__device__ __forceinline__ void cp16(uint32_t dst, const void* src, bool valid) {
    int sz = valid ? 16 : 0;
    asm volatile("cp.async.cg.shared.global [%0], [%1], 16, %2;"
                 :: "r"(dst), "l"(src), "r"(sz));
}
__device__ __forceinline__ uint32_t cvta_s(const void* p) {
    uint32_t a;
    asm("{ .reg .u64 t; cvta.to.shared.u64 t, %1; cvt.u32.u64 %0, t; }" : "=r"(a) : "l"(p));
    return a;
}

__global__ void __launch_bounds__(256) k_mma(
    const float* __restrict__ al, const float* __restrict__ ar_) {
    extern __shared__ __align__(16) char dsm[];
    uint32_t sm0 = cvta_s(dsm);

    int p = blockIdx.z;
    int m0 = blockIdx.y * 128, n0 = blockIdx.x * 128;
    int tid = threadIdx.x, wid = tid >> 5, lane = tid & 31;
    int wm = wid & 3, wn = wid >> 2;
    int grp = lane >> 2, tg = lane & 3;

    float acc[2][8][4];
    #pragma unroll
    for (int ms = 0; ms < 2; ms++)
        #pragma unroll
        for (int nt = 0; nt < 8; nt++)
            #pragma unroll
            for (int q = 0; q < 4; q++) acc[ms][nt][q] = 0.f;

    auto load_tile = [&](int kb, int buf) {
        uint32_t base = sm0 + buf * BUFB;
        #pragma unroll
        for (int t = 0; t < 4; t++) {
            int c = tid + t * 256;
            int row = c >> 3, seg = c & 7;
            int gm = m0 + row;
            cp16(base + row * 144 + seg * 16,
                 g_h2 + (size_t)gm * K2 + kb * BKK + seg * 8, gm < NN);
            cp16(base + SZA + row * 144 + seg * 16,
                 g_w2t + ((size_t)p * CIN + n0 + row) * K2 + kb * BKK + seg * 8, true);
        }
    };

    load_tile(0, 0);
    asm volatile("cp.async.commit_group;");

    for (int kb = 0; kb < K2 / BKK; kb++) {
        if (kb + 1 < K2 / BKK) load_tile(kb + 1, (kb + 1) & 1);
        asm volatile("cp.async.commit_group;");
        asm volatile("cp.async.wait_group 1;");
        __syncthreads();

        const __nv_bfloat16* sA = (const __nv_bfloat16*)(dsm + (kb & 1) * BUFB);
        const __nv_bfloat16* sB = (const __nv_bfloat16*)(dsm + (kb & 1) * BUFB + SZA);

        #pragma unroll
        for (int ks = 0; ks < BKK / 16; ks++) {
            int k0 = ks * 16;
            uint32_t afr[2][4];
            #pragma unroll
            for (int ms = 0; ms < 2; ms++) {
                int r = wm * 32 + ms * 16;
                afr[ms][0] = *(const uint32_t*)(sA + (r + grp)     * ASTR + k0 + tg * 2);
                afr[ms][1] = *(const uint32_t*)(sA + (r + grp + 8) * ASTR + k0 + tg * 2);
                afr[ms][2] = *(const uint32_t*)(sA + (r + grp)     * ASTR + k0 + tg * 2 + 8);
                afr[ms][3] = *(const uint32_t*)(sA + (r + grp + 8) * ASTR + k0 + tg * 2 + 8);
            }
            uint32_t bfr[8][2];
            #pragma unroll
            for (int nt = 0; nt < 8; nt++) {
                int nr = wn * 64 + nt * 8 + grp;
                bfr[nt][0] = *(const uint32_t*)(sB + nr * ASTR + k0 + tg * 2);
                bfr[nt][1] = *(const uint32_t*)(sB + nr * ASTR + k0 + tg * 2 + 8);
            }
            #pragma unroll
            for (int ms = 0; ms < 2; ms++)
                #pragma unroll
                for (int nt = 0; nt < 8; nt++)
                    mma_bf16(acc[ms][nt], afr[ms], bfr[nt]);
        }
        __syncthreads();
    }

    // epilogue: store fp16 feat + fused el/er (warp tile spans exactly one head)
    int head = (n0 >> 6) + wn;
    float alv[16], arv[16];
    #pragma unroll
    for (int nt = 0; nt < 8; nt++) {
        int d = nt * 8 + tg * 2;
        alv[nt*2+0] = al [(size_t)p * CIN + head * DD + d];
        alv[nt*2+1] = al [(size_t)p * CIN + head * DD + d + 1];
        arv[nt*2+0] = ar_[(size_t)p * CIN + head * DD + d];
        arv[nt*2+1] = ar_[(size_t)p * CIN + head * DD + d + 1];
    }
    #pragma unroll
    for (int ms = 0; ms < 2; ms++) {
        int r0 = m0 + wm * 32 + ms * 16 + grp;
        int r1 = r0 + 8;
        float el0 = 0.f, er0 = 0.f, el1 = 0.f, er1 = 0.f;
        #pragma unroll
        for (int nt = 0; nt < 8; nt++) {
            float c0 = acc[ms][nt][0], c1 = acc[ms][nt][1];
            float c2 = acc[ms][nt][2], c3 = acc[ms][nt][3];
            el0 += c0 * alv[nt*2] + c1 * alv[nt*2+1];
            er0 += c0 * arv[nt*2] + c1 * arv[nt*2+1];
            el1 += c2 * alv[nt*2] + c3 * alv[nt*2+1];
            er1 += c2 * arv[nt*2] + c3 * arv[nt*2+1];
            int col = n0 + wn * 64 + nt * 8 + tg * 2;
            if (r0 < NN)
                *(__half2*)(g_f16 + ((size_t)p * NN + r0) * CIN + col) = __floats2half2_rn(c0, c1);
            if (r1 < NN)
                *(__half2*)(g_f16 + ((size_t)p * NN + r1) * CIN + col) = __floats2half2_rn(c2, c3);
        }
        #pragma unroll
        for (int off = 1; off < 4; off <<= 1) {
            el0 += __shfl_xor_sync(0xffffffffu, el0, off);
            er0 += __shfl_xor_sync(0xffffffffu, er0, off);
            el1 += __shfl_xor_sync(0xffffffffu, el1, off);
            er1 += __shfl_xor_sync(0xffffffffu, er1, off);
        }
        if (tg == 0) {
            if (r0 < NN) {
                g_el[((size_t)p * NN + r0) * HH + head] = el0;
                g_er[((size_t)p * NN + r0) * HH + head] = er0;
            }
            if (r1 < NN) {
                g_el[((size_t)p * NN + r1) * HH + head] = el1;
                g_er[((size_t)p * NN + r1) * HH + head] = er1;
            }
        }
    }
}

// ---------------- CSR build ----------------
__global__ void k_hist(const int* __restrict__ dst) {
    int e = blockIdx.x * blockDim.x + threadIdx.x;
    int p = blockIdx.z;
    if (e < EE) atomicAdd(&g_deg[p * NN + dst[(size_t)p * EE + e]], 1);
}

__device__ __forceinline__ int warp_incl_scan(int v, int lane) {
    #pragma unroll
    for (int off = 1; off < 32; off <<= 1) {
        int t = __shfl_up_sync(0xffffffffu, v, off);
        if (lane >= off) v += t;
    }
    return v;
}

__global__ void k_scanA() {
    int p = blockIdx.z, b = blockIdx.x, tid = threadIdx.x;
    int lane = tid & 31, wid = tid >> 5;
    __shared__ int ws[32];
    int idx = b * 1024 + tid;
    int v = (idx < NN) ? g_deg[p * NN + idx] : 0;
    #pragma unroll
    for (int off = 16; off; off >>= 1) v += __shfl_xor_sync(0xffffffffu, v, off);
    if (lane == 0) ws[wid] = v;
    __syncthreads();
    if (wid == 0) {
        int s = ws[lane];
        #pragma unroll
        for (int off = 16; off; off >>= 1) s += __shfl_xor_sync(0xffffffffu, s, off);
        if (lane == 0) g_bsum[p * 64 + b] = s;
    }
}
__global__ void k_scanB() {
    int p = blockIdx.z, tid = threadIdx.x;   // 64 threads
    int lane = tid & 31, w = tid >> 5;
    __shared__ int t0;
    int v = (tid < 49) ? g_bsum[p * 64 + tid] : 0;
    int sc = warp_incl_scan(v, lane);
    if (w == 0 && lane == 31) t0 = sc;
    __syncthreads();
    int incl = sc + (w == 1 ? t0 : 0);
    g_boff[p * 64 + tid] = incl - v;
}
__global__ void k_scanC() {
    int p = blockIdx.z, b = blockIdx.x, tid = threadIdx.x;
    int lane = tid & 31, wid = tid >> 5;
    __shared__ int ws[32];
    int idx = b * 1024 + tid;
    int v = (idx < NN) ? g_deg[p * NN + idx] : 0;
    int sc = warp_incl_scan(v, lane);
    if (lane == 31) ws[wid] = sc;
    __syncthreads();
    if (wid == 0) ws[lane] = warp_incl_scan(ws[lane], lane);
    __syncthreads();
    int incl = sc + (wid > 0 ? ws[wid - 1] : 0) + g_boff[p * 64 + b];
    if (idx < NN) {
        g_rowptr[p * (NN + 1) + idx + 1] = incl;
        g_cur[p * NN + idx] = incl - v;
    }
    if (b == 0 && tid == 0) g_rowptr[p * (NN + 1)] = 0;
}

__global__ void k_fill(const int* __restrict__ dst, const int* __restrict__ src) {
    int e = blockIdx.x * blockDim.x + threadIdx.x;
    int p = blockIdx.z;
    if (e >= EE) return;
    int d = dst[(size_t)p * EE + e];
    int pos = atomicAdd(&g_cur[p * NN + d], 1);
    g_eidx[(size_t)p * EE + pos] = e;
    g_esrc[(size_t)p * EE + pos] = src[(size_t)p * EE + e];
}

// ---------------- K5: fused GAT per dst node (warp per node) + BN stats ----------------
__device__ __forceinline__ float lrelu(float v) { return v > 0.f ? v : SLOPE * v; }
#define ONLINE_UPD(v, m, d) \
    do { if ((v) > (m)) { (d) = (d) * __expf((m) - (v)) + 1.f; (m) = (v); } \
         else (d) += __expf((v) - (m)); } while (0)
#define CAP 64

__global__ void __launch_bounds__(256) k_gat(
    int p, const float* __restrict__ h, float* __restrict__ attn_out) {
    __shared__ float s_v  [8][CAP][4];   // cached leaky-relu scores (pass A -> pass B)
    __shared__ int   s_src[8][CAP];      // cached src ids
    __shared__ float s_a  [8][32][4];    // per-block alphas
    __shared__ float s_x  [8][CIN];      // BN transpose-reduce buffer

    int tid = threadIdx.x;
    int lane = tid & 31, wid = tid >> 5;
    int n = blockIdx.x * 8 + wid;        // NN = 6250 * 8, always < NN
    int beg = g_rowptr[p * (NN + 1) + n];
    int end = g_rowptr[p * (NN + 1) + n + 1];
    int myhead = lane >> 3;

    float acc[8];
    #pragma unroll
    for (int q = 0; q < 8; q++) acc[q] = 0.f;

    if (end > beg) {
        float4 er4 = *(const float4*)(g_er + ((size_t)p * NN + n) * HH);

        // pass A: online softmax + cache v/src in smem
        float m0 = -1e30f, m1 = -1e30f, m2 = -1e30f, m3 = -1e30f;
        float d0 = 0.f, d1 = 0.f, d2 = 0.f, d3 = 0.f;
        for (int j = beg + lane; j < end; j += 32) {
            int s = g_esrc[(size_t)p * EE + j];
            float4 el4 = *(const float4*)(g_el + ((size_t)p * NN + s) * HH);
            float v0 = lrelu(el4.x + er4.x), v1 = lrelu(el4.y + er4.y);
            float v2 = lrelu(el4.z + er4.z), v3 = lrelu(el4.w + er4.w);
            int slot = j - beg;
            if (slot < CAP) {
                s_src[wid][slot] = s;
                *(float4*)s_v[wid][slot] = make_float4(v0, v1, v2, v3);
            }
            ONLINE_UPD(v0, m0, d0); ONLINE_UPD(v1, m1, d1);
            ONLINE_UPD(v2, m2, d2); ONLINE_UPD(v3, m3, d3);
        }
        float M0 = m0, M1 = m1, M2 = m2, M3 = m3;
        #pragma unroll
        for (int off = 16; off; off >>= 1) {
            M0 = fmaxf(M0, __shfl_xor_sync(0xffffffffu, M0, off));
            M1 = fmaxf(M1, __shfl_xor_sync(0xffffffffu, M1, off));
            M2 = fmaxf(M2, __shfl_xor_sync(0xffffffffu, M2, off));
            M3 = fmaxf(M3, __shfl_xor_sync(0xffffffffu, M3, off));
        }
        d0 *= __expf(m0 - M0); d1 *= __expf(m1 - M1);
        d2 *= __expf(m2 - M2); d3 *= __expf(m3 - M3);
        #pragma unroll
        for (int off = 16; off; off >>= 1) {
            d0 += __shfl_xor_sync(0xffffffffu, d0, off);
            d1 += __shfl_xor_sync(0xffffffffu, d1, off);
            d2 += __shfl_xor_sync(0xffffffffu, d2, off);
            d3 += __shfl_xor_sync(0xffffffffu, d3, off);
        }
        float i0 = d0 > 0.f ? 1.f / d0 : 0.f;
        float i1 = d1 > 0.f ? 1.f / d1 : 0.f;
        float i2 = d2 > 0.f ? 1.f / d2 : 0.f;
        float i3 = d3 > 0.f ? 1.f / d3 : 0.f;

        // pass B blocks of 32 edges
        for (int jb = beg; jb < end; jb += 32) {
            int j = jb + lane;
            int sj = 0;
            if (j < end) {
                int slot = j - beg;
                float4 v4;
                if (slot < CAP) {
                    v4 = *(const float4*)s_v[wid][slot];
                    sj = s_src[wid][slot];
                } else {                                  // ultra-rare overflow
                    sj = g_esrc[(size_t)p * EE + j];
                    float4 el4 = *(const float4*)(g_el + ((size_t)p * NN + sj) * HH);
                    v4 = make_float4(lrelu(el4.x + er4.x), lrelu(el4.y + er4.y),
                                     lrelu(el4.z + er4.z), lrelu(el4.w + er4.w));
                }
                float a0 = __expf(v4.x - M0) * i0;
                float a1 = __expf(v4.y - M1) * i1;
                float a2 = __expf(v4.z - M2) * i2;
                float a3 = __expf(v4.w - M3) * i3;
                *(float4*)s_a[wid][lane] = make_float4(a0, a1, a2, a3);
                int eid = g_eidx[(size_t)p * EE + j];
                attn_out[(size_t)p * EE + eid] = 0.25f * (a0 + a1 + a2 + a3);
            }
            __syncwarp();
            int cnt = min(32, end - jb);
            int tb = jb - beg;
            int t = 0;
            for (; t + 1 < cnt; t += 2) {
                int t0g = tb + t, t1g = t0g + 1;
                int s0 = (t0g < CAP) ? s_src[wid][t0g] : __shfl_sync(0xffffffffu, sj, t);
                int s1 = (t1g < CAP) ? s_src[wid][t1g] : __shfl_sync(0xffffffffu, sj, t + 1);
                uint4 q0 = ((const uint4*)(g_f16 + ((size_t)p * NN + s0) * CIN))[lane];
                uint4 q1 = ((const uint4*)(g_f16 + ((size_t)p * NN + s1) * CIN))[lane];
                float w0 = s_a[wid][t][myhead];
                float w1 = s_a[wid][t + 1][myhead];
                const __half2* ha = (const __half2*)&q0;
                const __half2* hb = (const __half2*)&q1;
                #pragma unroll
                for (int q = 0; q < 4; q++) {
                    float2 ua = __half22float2(ha[q]);
                    float2 ub = __half22float2(hb[q]);
                    acc[q*2+0] += ua.x * w0 + ub.x * w1;
                    acc[q*2+1] += ua.y * w0 + ub.y * w1;
                }
            }
            if (t < cnt) {
                int t0g = tb + t;
                int s0 = (t0g < CAP) ? s_src[wid][t0g] : __shfl_sync(0xffffffffu, sj, t);
                uint4 q0 = ((const uint4*)(g_f16 + ((size_t)p * NN + s0) * CIN))[lane];
                float w0 = s_a[wid][t][myhead];
                const __half2* ha = (const __half2*)&q0;
                #pragma unroll
                for (int q = 0; q < 4; q++) {
                    float2 ua = __half22float2(ha[q]);
                    acc[q*2+0] += ua.x * w0;
                    acc[q*2+1] += ua.y * w0;
                }
            }
            __syncwarp();
        }
    }

    // epilogue: x = relu(out) + h over channels lane*8..+8
    int cb = lane * 8;
    float4 h0 = *(const float4*)(h + (size_t)n * CIN + cb);
    float4 h1 = *(const float4*)(h + (size_t)n * CIN + cb + 4);
    float x[8];
    x[0] = fmaxf(acc[0], 0.f) + h0.x; x[1] = fmaxf(acc[1], 0.f) + h0.y;
    x[2] = fmaxf(acc[2], 0.f) + h0.z; x[3] = fmaxf(acc[3], 0.f) + h0.w;
    x[4] = fmaxf(acc[4], 0.f) + h1.x; x[5] = fmaxf(acc[5], 0.f) + h1.y;
    x[6] = fmaxf(acc[6], 0.f) + h1.z; x[7] = fmaxf(acc[7], 0.f) + h1.w;
    float* op = g_accum + ((size_t)p * NN + n) * CIN + cb;
    *(float4*)(op)     = make_float4(x[0], x[1], x[2], x[3]);
    *(float4*)(op + 4) = make_float4(x[4], x[5], x[6], x[7]);

    // BN stats: transpose-reduce through smem (no smem atomics)
    *(float4*)&s_x[wid][cb]     = make_float4(x[0], x[1], x[2], x[3]);
    *(float4*)&s_x[wid][cb + 4] = make_float4(x[4], x[5], x[6], x[7]);
    __syncthreads();
    float ssum = 0.f, ssq = 0.f;
    #pragma unroll
    for (int w = 0; w < 8; w++) {
        float v = s_x[w][tid];
        ssum += v; ssq += v * v;
    }
    atomicAdd(&g_sum[p * CIN + tid], ssum);
    atomicAdd(&g_sumsq[p * CIN + tid], ssq);
}

// ---------------- K7: BN affine ----------------
__global__ void k_bnfin(const float* __restrict__ gamma, const float* __restrict__ beta) {
    int p = blockIdx.z; int c = threadIdx.x;
    float mu  = g_sum[p * CIN + c] * (1.f / NN);
    float var = g_sumsq[p * CIN + c] * (1.f / NN) - mu * mu;
    float sc = gamma[c] * rsqrtf(var + EPS);
    g_scale[p * CIN + c] = sc;
    g_shift[p * CIN + c] = beta[c] - sc * mu;
}

// ---------------- K8: pooled output ----------------
__global__ void k_pool(const float* __restrict__ wmat, float* __restrict__ pooled) {
    int idx = blockIdx.x * blockDim.x + threadIdx.x;
    if (idx >= NN * 64) return;
    int n = idx >> 6, c4 = (idx & 63) * 4;
    float4 acc = make_float4(0.f, 0.f, 0.f, 0.f);
    #pragma unroll
    for (int p = 0; p < PP; p++) {
        float wv = wmat[n * PP + p];
        float4 x  = *(const float4*)(g_accum + ((size_t)p * NN + n) * CIN + c4);
        float4 sc = *(const float4*)(g_scale + p * CIN + c4);
        float4 sh = *(const float4*)(g_shift + p * CIN + c4);
        acc.x += wv * (sc.x * x.x + sh.x);
        acc.y += wv * (sc.y * x.y + sh.y);
        acc.z += wv * (sc.z * x.z + sh.z);
        acc.w += wv * (sc.w * x.w + sh.w);
    }
    *(float4*)(pooled + (size_t)n * CIN + c4) = acc;
}

// ---------------- host ----------------
extern "C" void kernel_launch(void* const* d_in, const int* in_sizes, int n_in,
                              void* d_out, int out_size) {
    const float* h     = (const float*)d_in[0];
    const float* mask  = (const float*)d_in[1];
    const int*   src   = (const int*)  d_in[2];
    const int*   dst   = (const int*)  d_in[3];
    const float* fc    = (const float*)d_in[4];
    const float* al    = (const float*)d_in[5];
    const float* ar    = (const float*)d_in[6];
    const float* gamma = (const float*)d_in[7];
    const float* beta  = (const float*)d_in[8];

    float* out    = (float*)d_out;
    float* pooled = out;
    float* wout   = out + (size_t)NN * CIN;
    float* attn   = wout + (size_t)NN * PP;

    cudaFuncSetAttribute(k_mma, cudaFuncAttributeMaxDynamicSharedMemorySize, SMTOT);

    k_zero<<<(PP * NN + 255) / 256, 256>>>();
    k_cvt_h<<<(int)(((size_t)NN * CIN + 255) / 256), 256>>>(h);
    k_cvt_w<<<(PP * CIN * CIN + 255) / 256, 256>>>(fc);

    dim3 gm(CIN / 128, (NN + 127) / 128, PP);
    k_mma<<<gm, 256, SMTOT>>>(al, ar);

    k_w<<<(NN + 255) / 256, 256>>>(mask, wout);

    k_hist<<<dim3((EE + 255) / 256, 1, PP), 256>>>(dst);
    k_scanA<<<dim3(49, 1, PP), 1024>>>();
    k_scanB<<<dim3(1, 1, PP), 64>>>();
    k_scanC<<<dim3(49, 1, PP), 1024>>>();
    k_fill<<<dim3((EE + 255) / 256, 1, PP), 256>>>(dst, src);

    for (int p = 0; p < PP; p++)
        k_gat<<<NN / 8, 256>>>(p, h, attn);

    k_bnfin<<<dim3(1, 1, PP), 256>>>(gamma, beta);
    k_pool<<<(NN * 64 + 255) / 256, 256>>>(wout, pooled);
}

// round 14
// speedup vs baseline: 1.5827x; 1.0419x over previous
#include <cuda_runtime.h>
#include <cuda_bf16.h>
#include <cuda_fp16.h>
#include <cstdint>

#define NN   50000
#define EE   800000
#define PP   3
#define HH   4
#define DD   64
#define CIN  256          // H*D = in_size
#define K2   256          // GEMM K (bf16 hi only; lo terms negligible)
#define EPS  1e-5f
#define SLOPE 0.2f

// ---------------- device scratch (static, no allocation) ----------------
__device__ __align__(256) __half g_f16 [(size_t)PP*NN*CIN];   // fp16 projected features
__device__ __align__(256) float g_accum[(size_t)PP*NN*CIN];
__device__ __align__(256) __nv_bfloat16 g_h2 [(size_t)NN*K2];
__device__ __align__(256) __nv_bfloat16 g_w2t[(size_t)PP*CIN*K2];
__device__ __align__(16)  float g_el   [PP*NN*HH];
__device__ __align__(16)  float g_er   [PP*NN*HH];
__device__ int g_deg   [PP*NN];
__device__ int g_rowptr[PP*(NN+1)];
__device__ int g_cur   [PP*NN];
__device__ int g_bsum  [PP*64];
__device__ int g_boff  [PP*64];
__device__ int g_eidx  [(size_t)PP*EE];
__device__ int g_esrc  [(size_t)PP*EE];
__device__ float g_sum  [PP*CIN];
__device__ float g_sumsq[PP*CIN];
__device__ float g_scale[PP*CIN];
__device__ float g_shift[PP*CIN];

// ---------------- K_prep: fused zero + weights + conversions ----------------
__global__ void k_prep(const float* __restrict__ h, const float* __restrict__ fc,
                       const float* __restrict__ mask, float* __restrict__ wout) {
    size_t i = (size_t)blockIdx.x * blockDim.x + threadIdx.x;
    if (i < (size_t)NN * CIN)
        g_h2[i] = __float2bfloat16(h[i]);
    if (i < PP * CIN * CIN) {
        int p = (int)(i >> 16), rem = (int)(i & 65535);
        int k = rem >> 8, n = rem & 255;
        g_w2t[((size_t)p * CIN + n) * K2 + k] = __float2bfloat16(fc[i]);
    }
    if (i < PP * NN) g_deg[i] = 0;
    if (i < PP * CIN) { g_sum[i] = 0.f; g_sumsq[i] = 0.f; }
    if (i < NN) {
        float m0 = mask[i*PP+0], m1 = mask[i*PP+1], m2 = mask[i*PP+2];
        float inv = 1.f / (m0 + m1 + m2);
        wout[i*PP+0] = m0 * inv;
        wout[i*PP+1] = m1 * inv;
        wout[i*PP+2] = m2 * inv;
    }
}

// ---------------- K1: HMMA bf16 GEMM, cp.async + ldmatrix ----------------
#define BKK 64
#define ASTR 72                         // bf16 units; 144 B row stride
#define SZA (128 * ASTR * 2)            // 18432 B per tile
#define BUFB (2 * SZA)                  // A + B per buffer
#define SMTOT (2 * BUFB)                // 73728 B

__device__ __forceinline__ void mma_bf16(float* c, const uint32_t* a, const uint32_t* b) {
    asm volatile("mma.sync.aligned.m16n8k16.row.col.f32.bf16.bf16.f32 "
        "{%0,%1,%2,%3}, {%4,%5,%6,%7}, {%8,%9}, {%0,%1,%2,%3};"
        : "+f"(c[0]), "+f"(c[1]), "+f"(c[2]), "+f"(c[3])
        : "r"(a[0]), "r"(a[1]), "r"(a[2]), "r"(a[3]), "r"(b[0]), "r"(b[1]));
}
__device__ __forceinline__ void ldmx4(uint32_t* r, uint32_t addr) {
    asm volatile("ldmatrix.sync.aligned.m8n8.x4.shared.b16 {%0,%1,%2,%3}, [%4];"
        : "=r"(r[0]), "=r"(r[1]), "=r"(r[2]), "=r"(r[3]) : "r"(addr));
}
__device__ __forceinline__ void cp16(uint32_t dst, const void* src, bool valid) {
    int sz = valid ? 16 : 0;
    asm volatile("cp.async.cg.shared.global [%0], [%1], 16, %2;"
                 :: "r"(dst), "l"(src), "r"(sz));
}
__device__ __forceinline__ uint32_t cvta_s(const void* p) {
    uint32_t a;
    asm("{ .reg .u64 t; cvta.to.shared.u64 t, %1; cvt.u32.u64 %0, t; }" : "=r"(a) : "l"(p));
    return a;
}

__global__ void __launch_bounds__(256) k_mma(
    const float* __restrict__ al, const float* __restrict__ ar_) {
    extern __shared__ __align__(16) char dsm[];
    uint32_t sm0 = cvta_s(dsm);

    int p = blockIdx.z;
    int m0 = blockIdx.y * 128, n0 = blockIdx.x * 128;
    int tid = threadIdx.x, wid = tid >> 5, lane = tid & 31;
    int wm = wid & 3, wn = wid >> 2;
    int grp = lane >> 2, tg = lane & 3;

    // per-lane ldmatrix byte offsets (within buffer)
    int rlA = (lane & 7) + ((lane >> 3) & 1) * 8;    // row-in-16 for A matrices
    int kbA = ((lane >> 4) & 1) * 16;                // k byte off (0 or 16)
    uint32_t aoff0 = (uint32_t)((wm * 32 +      rlA) * 144 + kbA);
    uint32_t aoff1 = (uint32_t)((wm * 32 + 16 + rlA) * 144 + kbA);
    int gB = lane >> 3;
    int rlB = lane & 7;
    int ntl = gB >> 1;                                // 0/1 within pair
    int kbB = (gB & 1) * 16;
    uint32_t boff[4];
    #pragma unroll
    for (int j = 0; j < 4; j++)
        boff[j] = (uint32_t)((wn * 64 + (2 * j + ntl) * 8 + rlB) * 144 + kbB);

    float acc[2][8][4];
    #pragma unroll
    for (int ms = 0; ms < 2; ms++)
        #pragma unroll
        for (int nt = 0; nt < 8; nt++)
            #pragma unroll
            for (int q = 0; q < 4; q++) acc[ms][nt][q] = 0.f;

    auto load_tile = [&](int kb, int buf) {
        uint32_t base = sm0 + buf * BUFB;
        #pragma unroll
        for (int t = 0; t < 4; t++) {
            int c = tid + t * 256;
            int row = c >> 3, seg = c & 7;
            int gm = m0 + row;
            cp16(base + row * 144 + seg * 16,
                 g_h2 + (size_t)gm * K2 + kb * BKK + seg * 8, gm < NN);
            cp16(base + SZA + row * 144 + seg * 16,
                 g_w2t + ((size_t)p * CIN + n0 + row) * K2 + kb * BKK + seg * 8, true);
        }
    };

    load_tile(0, 0);
    asm volatile("cp.async.commit_group;");

    for (int kb = 0; kb < K2 / BKK; kb++) {
        if (kb + 1 < K2 / BKK) load_tile(kb + 1, (kb + 1) & 1);
        asm volatile("cp.async.commit_group;");
        asm volatile("cp.async.wait_group 1;");
        __syncthreads();

        uint32_t sA32 = sm0 + (kb & 1) * BUFB;
        uint32_t sB32 = sA32 + SZA;

        #pragma unroll
        for (int ks = 0; ks < BKK / 16; ks++) {
            uint32_t k0b = ks * 32;                   // 16 halves = 32 bytes
            uint32_t afr[2][4];
            ldmx4(afr[0], sA32 + aoff0 + k0b);
            ldmx4(afr[1], sA32 + aoff1 + k0b);
            uint32_t bq[4][4];
            #pragma unroll
            for (int j = 0; j < 4; j++)
                ldmx4(bq[j], sB32 + boff[j] + k0b);
            #pragma unroll
            for (int ms = 0; ms < 2; ms++)
                #pragma unroll
                for (int nt = 0; nt < 8; nt++)
                    mma_bf16(acc[ms][nt], afr[ms], &bq[nt >> 1][(nt & 1) * 2]);
        }
        __syncthreads();
    }

    // epilogue: store fp16 feat + fused el/er (warp tile spans exactly one head)
    int head = (n0 >> 6) + wn;
    float alv[16], arv[16];
    #pragma unroll
    for (int nt = 0; nt < 8; nt++) {
        int d = nt * 8 + tg * 2;
        alv[nt*2+0] = al [(size_t)p * CIN + head * DD + d];
        alv[nt*2+1] = al [(size_t)p * CIN + head * DD + d + 1];
        arv[nt*2+0] = ar_[(size_t)p * CIN + head * DD + d];
        arv[nt*2+1] = ar_[(size_t)p * CIN + head * DD + d + 1];
    }
    #pragma unroll
    for (int ms = 0; ms < 2; ms++) {
        int r0 = m0 + wm * 32 + ms * 16 + grp;
        int r1 = r0 + 8;
        float el0 = 0.f, er0 = 0.f, el1 = 0.f, er1 = 0.f;
        #pragma unroll
        for (int nt = 0; nt < 8; nt++) {
            float c0 = acc[ms][nt][0], c1 = acc[ms][nt][1];
            float c2 = acc[ms][nt][2], c3 = acc[ms][nt][3];
            el0 += c0 * alv[nt*2] + c1 * alv[nt*2+1];
            er0 += c0 * arv[nt*2] + c1 * arv[nt*2+1];
            el1 += c2 * alv[nt*2] + c3 * alv[nt*2+1];
            er1 += c2 * arv[nt*2] + c3 * arv[nt*2+1];
            int col = n0 + wn * 64 + nt * 8 + tg * 2;
            if (r0 < NN)
                *(__half2*)(g_f16 + ((size_t)p * NN + r0) * CIN + col) = __floats2half2_rn(c0, c1);
            if (r1 < NN)
                *(__half2*)(g_f16 + ((size_t)p * NN + r1) * CIN + col) = __floats2half2_rn(c2, c3);
        }
        #pragma unroll
        for (int off = 1; off < 4; off <<= 1) {
            el0 += __shfl_xor_sync(0xffffffffu, el0, off);
            er0 += __shfl_xor_sync(0xffffffffu, er0, off);
            el1 += __shfl_xor_sync(0xffffffffu, el1, off);
            er1 += __shfl_xor_sync(0xffffffffu, er1, off);
        }
        if (tg == 0) {
            if (r0 < NN) {
                g_el[((size_t)p * NN + r0) * HH + head] = el0;
                g_er[((size_t)p * NN + r0) * HH + head] = er0;
            }
            if (r1 < NN) {
                g_el[((size_t)p * NN + r1) * HH + head] = el1;
                g_er[((size_t)p * NN + r1) * HH + head] = er1;
            }
        }
    }
}

// ---------------- CSR build ----------------
__global__ void k_hist(const int* __restrict__ dst) {
    int e = blockIdx.x * blockDim.x + threadIdx.x;
    int p = blockIdx.z;
    if (e < EE) atomicAdd(&g_deg[p * NN + dst[(size_t)p * EE + e]], 1);
}

__device__ __forceinline__ int warp_incl_scan(int v, int lane) {
    #pragma unroll
    for (int off = 1; off < 32; off <<= 1) {
        int t = __shfl_up_sync(0xffffffffu, v, off);
        if (lane >= off) v += t;
    }
    return v;
}

__global__ void k_scanA() {
    int p = blockIdx.z, b = blockIdx.x, tid = threadIdx.x;
    int lane = tid & 31, wid = tid >> 5;
    __shared__ int ws[32];
    int idx = b * 1024 + tid;
    int v = (idx < NN) ? g_deg[p * NN + idx] : 0;
    #pragma unroll
    for (int off = 16; off; off >>= 1) v += __shfl_xor_sync(0xffffffffu, v, off);
    if (lane == 0) ws[wid] = v;
    __syncthreads();
    if (wid == 0) {
        int s = ws[lane];
        #pragma unroll
        for (int off = 16; off; off >>= 1) s += __shfl_xor_sync(0xffffffffu, s, off);
        if (lane == 0) g_bsum[p * 64 + b] = s;
    }
}
__global__ void k_scanB() {
    int p = blockIdx.z, tid = threadIdx.x;   // 64 threads
    int lane = tid & 31, w = tid >> 5;
    __shared__ int t0;
    int v = (tid < 49) ? g_bsum[p * 64 + tid] : 0;
    int sc = warp_incl_scan(v, lane);
    if (w == 0 && lane == 31) t0 = sc;
    __syncthreads();
    int incl = sc + (w == 1 ? t0 : 0);
    g_boff[p * 64 + tid] = incl - v;
}
__global__ void k_scanC() {
    int p = blockIdx.z, b = blockIdx.x, tid = threadIdx.x;
    int lane = tid & 31, wid = tid >> 5;
    __shared__ int ws[32];
    int idx = b * 1024 + tid;
    int v = (idx < NN) ? g_deg[p * NN + idx] : 0;
    int sc = warp_incl_scan(v, lane);
    if (lane == 31) ws[wid] = sc;
    __syncthreads();
    if (wid == 0) ws[lane] = warp_incl_scan(ws[lane], lane);
    __syncthreads();
    int incl = sc + (wid > 0 ? ws[wid - 1] : 0) + g_boff[p * 64 + b];
    if (idx < NN) {
        g_rowptr[p * (NN + 1) + idx + 1] = incl;
        g_cur[p * NN + idx] = incl - v;
    }
    if (b == 0 && tid == 0) g_rowptr[p * (NN + 1)] = 0;
}

__global__ void k_fill(const int* __restrict__ dst, const int* __restrict__ src) {
    int e = blockIdx.x * blockDim.x + threadIdx.x;
    int p = blockIdx.z;
    if (e >= EE) return;
    int d = dst[(size_t)p * EE + e];
    int pos = atomicAdd(&g_cur[p * NN + d], 1);
    g_eidx[(size_t)p * EE + pos] = e;
    g_esrc[(size_t)p * EE + pos] = src[(size_t)p * EE + e];
}

// ---------------- K5: fused GAT per dst node (warp per node) + BN stats ----------------
__device__ __forceinline__ float lrelu(float v) { return v > 0.f ? v : SLOPE * v; }
#define ONLINE_UPD(v, m, d) \
    do { if ((v) > (m)) { (d) = (d) * __expf((m) - (v)) + 1.f; (m) = (v); } \
         else (d) += __expf((v) - (m)); } while (0)
#define CAP 64

__global__ void __launch_bounds__(256) k_gat(
    int p, const float* __restrict__ h, float* __restrict__ attn_out) {
    __shared__ float s_v  [8][CAP][4];   // cached leaky-relu scores (pass A -> pass B)
    __shared__ int   s_src[8][CAP];      // cached src ids
    __shared__ float s_a  [8][32][4];    // per-block alphas
    __shared__ float s_x  [8][CIN];      // BN transpose-reduce buffer

    int tid = threadIdx.x;
    int lane = tid & 31, wid = tid >> 5;
    int n = blockIdx.x * 8 + wid;        // NN = 6250 * 8, always < NN
    int beg = g_rowptr[p * (NN + 1) + n];
    int end = g_rowptr[p * (NN + 1) + n + 1];
    int myhead = lane >> 3;

    float acc[8];
    #pragma unroll
    for (int q = 0; q < 8; q++) acc[q] = 0.f;

    if (end > beg) {
        float4 er4 = *(const float4*)(g_er + ((size_t)p * NN + n) * HH);

        // pass A: online softmax + cache v/src in smem
        float m0 = -1e30f, m1 = -1e30f, m2 = -1e30f, m3 = -1e30f;
        float d0 = 0.f, d1 = 0.f, d2 = 0.f, d3 = 0.f;
        for (int j = beg + lane; j < end; j += 32) {
            int s = g_esrc[(size_t)p * EE + j];
            float4 el4 = *(const float4*)(g_el + ((size_t)p * NN + s) * HH);
            float v0 = lrelu(el4.x + er4.x), v1 = lrelu(el4.y + er4.y);
            float v2 = lrelu(el4.z + er4.z), v3 = lrelu(el4.w + er4.w);
            int slot = j - beg;
            if (slot < CAP) {
                s_src[wid][slot] = s;
                *(float4*)s_v[wid][slot] = make_float4(v0, v1, v2, v3);
            }
            ONLINE_UPD(v0, m0, d0); ONLINE_UPD(v1, m1, d1);
            ONLINE_UPD(v2, m2, d2); ONLINE_UPD(v3, m3, d3);
        }
        float M0 = m0, M1 = m1, M2 = m2, M3 = m3;
        #pragma unroll
        for (int off = 16; off; off >>= 1) {
            M0 = fmaxf(M0, __shfl_xor_sync(0xffffffffu, M0, off));
            M1 = fmaxf(M1, __shfl_xor_sync(0xffffffffu, M1, off));
            M2 = fmaxf(M2, __shfl_xor_sync(0xffffffffu, M2, off));
            M3 = fmaxf(M3, __shfl_xor_sync(0xffffffffu, M3, off));
        }
        d0 *= __expf(m0 - M0); d1 *= __expf(m1 - M1);
        d2 *= __expf(m2 - M2); d3 *= __expf(m3 - M3);
        #pragma unroll
        for (int off = 16; off; off >>= 1) {
            d0 += __shfl_xor_sync(0xffffffffu, d0, off);
            d1 += __shfl_xor_sync(0xffffffffu, d1, off);
            d2 += __shfl_xor_sync(0xffffffffu, d2, off);
            d3 += __shfl_xor_sync(0xffffffffu, d3, off);
        }
        float i0 = d0 > 0.f ? 1.f / d0 : 0.f;
        float i1 = d1 > 0.f ? 1.f / d1 : 0.f;
        float i2 = d2 > 0.f ? 1.f / d2 : 0.f;
        float i3 = d3 > 0.f ? 1.f / d3 : 0.f;

        // pass B blocks of 32 edges
        for (int jb = beg; jb < end; jb += 32) {
            int j = jb + lane;
            int sj = 0;
            if (j < end) {
                int slot = j - beg;
                float4 v4;
                if (slot < CAP) {
                    v4 = *(const float4*)s_v[wid][slot];
                    sj = s_src[wid][slot];
                } else {                                  // ultra-rare overflow
                    sj = g_esrc[(size_t)p * EE + j];
                    float4 el4 = *(const float4*)(g_el + ((size_t)p * NN + sj) * HH);
                    v4 = make_float4(lrelu(el4.x + er4.x), lrelu(el4.y + er4.y),
                                     lrelu(el4.z + er4.z), lrelu(el4.w + er4.w));
                }
                float a0 = __expf(v4.x - M0) * i0;
                float a1 = __expf(v4.y - M1) * i1;
                float a2 = __expf(v4.z - M2) * i2;
                float a3 = __expf(v4.w - M3) * i3;
                *(float4*)s_a[wid][lane] = make_float4(a0, a1, a2, a3);
                int eid = g_eidx[(size_t)p * EE + j];
                attn_out[(size_t)p * EE + eid] = 0.25f * (a0 + a1 + a2 + a3);
            }
            __syncwarp();
            int cnt = min(32, end - jb);
            int tb = jb - beg;
            const __half* fbase = g_f16 + (size_t)p * NN * CIN;
            int t = 0;
            for (; t + 3 < cnt; t += 4) {
                int s0, s1, s2, s3;
                int t0g = tb + t;
                if (t0g + 3 < CAP) {
                    s0 = s_src[wid][t0g];     s1 = s_src[wid][t0g + 1];
                    s2 = s_src[wid][t0g + 2]; s3 = s_src[wid][t0g + 3];
                } else {
                    s0 = __shfl_sync(0xffffffffu, sj, t);
                    s1 = __shfl_sync(0xffffffffu, sj, t + 1);
                    s2 = __shfl_sync(0xffffffffu, sj, t + 2);
                    s3 = __shfl_sync(0xffffffffu, sj, t + 3);
                }
                uint4 q0 = ((const uint4*)(fbase + (size_t)s0 * CIN))[lane];
                uint4 q1 = ((const uint4*)(fbase + (size_t)s1 * CIN))[lane];
                uint4 q2 = ((const uint4*)(fbase + (size_t)s2 * CIN))[lane];
                uint4 q3 = ((const uint4*)(fbase + (size_t)s3 * CIN))[lane];
                float w0 = s_a[wid][t][myhead];
                float w1 = s_a[wid][t + 1][myhead];
                float w2 = s_a[wid][t + 2][myhead];
                float w3 = s_a[wid][t + 3][myhead];
                const __half2* ha = (const __half2*)&q0;
                const __half2* hb = (const __half2*)&q1;
                const __half2* hc = (const __half2*)&q2;
                const __half2* hd = (const __half2*)&q3;
                #pragma unroll
                for (int q = 0; q < 4; q++) {
                    float2 ua = __half22float2(ha[q]);
                    float2 ub = __half22float2(hb[q]);
                    float2 uc = __half22float2(hc[q]);
                    float2 ud = __half22float2(hd[q]);
                    acc[q*2+0] += ua.x * w0 + ub.x * w1 + uc.x * w2 + ud.x * w3;
                    acc[q*2+1] += ua.y * w0 + ub.y * w1 + uc.y * w2 + ud.y * w3;
                }
            }
            for (; t < cnt; t++) {
                int t0g = tb + t;
                int s0 = (t0g < CAP) ? s_src[wid][t0g] : __shfl_sync(0xffffffffu, sj, t);
                uint4 q0 = ((const uint4*)(fbase + (size_t)s0 * CIN))[lane];
                float w0 = s_a[wid][t][myhead];
                const __half2* ha = (const __half2*)&q0;
                #pragma unroll
                for (int q = 0; q < 4; q++) {
                    float2 ua = __half22float2(ha[q]);
                    acc[q*2+0] += ua.x * w0;
                    acc[q*2+1] += ua.y * w0;
                }
            }
            __syncwarp();
        }
    }

    // epilogue: x = relu(out) + h over channels lane*8..+8
    int cb = lane * 8;
    float4 h0 = *(const float4*)(h + (size_t)n * CIN + cb);
    float4 h1 = *(const float4*)(h + (size_t)n * CIN + cb + 4);
    float x[8];
    x[0] = fmaxf(acc[0], 0.f) + h0.x; x[1] = fmaxf(acc[1], 0.f) + h0.y;
    x[2] = fmaxf(acc[2], 0.f) + h0.z; x[3] = fmaxf(acc[3], 0.f) + h0.w;
    x[4] = fmaxf(acc[4], 0.f) + h1.x; x[5] = fmaxf(acc[5], 0.f) + h1.y;
    x[6] = fmaxf(acc[6], 0.f) + h1.z; x[7] = fmaxf(acc[7], 0.f) + h1.w;
    float* op = g_accum + ((size_t)p * NN + n) * CIN + cb;
    *(float4*)(op)     = make_float4(x[0], x[1], x[2], x[3]);
    *(float4*)(op + 4) = make_float4(x[4], x[5], x[6], x[7]);

    // BN stats: transpose-reduce through smem (no smem atomics)
    *(float4*)&s_x[wid][cb]     = make_float4(x[0], x[1], x[2], x[3]);
    *(float4*)&s_x[wid][cb + 4] = make_float4(x[4], x[5], x[6], x[7]);
    __syncthreads();
    float ssum = 0.f, ssq = 0.f;
    #pragma unroll
    for (int w = 0; w < 8; w++) {
        float v = s_x[w][tid];
        ssum += v; ssq += v * v;
    }
    atomicAdd(&g_sum[p * CIN + tid], ssum);
    atomicAdd(&g_sumsq[p * CIN + tid], ssq);
}

// ---------------- K7: BN affine ----------------
__global__ void k_bnfin(const float* __restrict__ gamma, const float* __restrict__ beta) {
    int p = blockIdx.z; int c = threadIdx.x;
    float mu  = g_sum[p * CIN + c] * (1.f / NN);
    float var = g_sumsq[p * CIN + c] * (1.f / NN) - mu * mu;
    float sc = gamma[c] * rsqrtf(var + EPS);
    g_scale[p * CIN + c] = sc;
    g_shift[p * CIN + c] = beta[c] - sc * mu;
}

// ---------------- K8: pooled output ----------------
__global__ void k_pool(const float* __restrict__ wmat, float* __restrict__ pooled) {
    int idx = blockIdx.x * blockDim.x + threadIdx.x;
    if (idx >= NN * 64) return;
    int n = idx >> 6, c4 = (idx & 63) * 4;
    float4 acc = make_float4(0.f, 0.f, 0.f, 0.f);
    #pragma unroll
    for (int p = 0; p < PP; p++) {
        float wv = wmat[n * PP + p];
        float4 x  = *(const float4*)(g_accum + ((size_t)p * NN + n) * CIN + c4);
        float4 sc = *(const float4*)(g_scale + p * CIN + c4);
        float4 sh = *(const float4*)(g_shift + p * CIN + c4);
        acc.x += wv * (sc.x * x.x + sh.x);
        acc.y += wv * (sc.y * x.y + sh.y);
        acc.z += wv * (sc.z * x.z + sh.z);
        acc.w += wv * (sc.w * x.w + sh.w);
    }
    *(float4*)(pooled + (size_t)n * CIN + c4) = acc;
}

// ---------------- host ----------------
extern "C" void kernel_launch(void* const* d_in, const int* in_sizes, int n_in,
                              void* d_out, int out_size) {
    const float* h     = (const float*)d_in[0];
    const float* mask  = (const float*)d_in[1];
    const int*   src   = (const int*)  d_in[2];
    const int*   dst   = (const int*)  d_in[3];
    const float* fc    = (const float*)d_in[4];
    const float* al    = (const float*)d_in[5];
    const float* ar    = (const float*)d_in[6];
    const float* gamma = (const float*)d_in[7];
    const float* beta  = (const float*)d_in[8];

    float* out    = (float*)d_out;
    float* pooled = out;
    float* wout   = out + (size_t)NN * CIN;
    float* attn   = wout + (size_t)NN * PP;

    cudaFuncSetAttribute(k_mma, cudaFuncAttributeMaxDynamicSharedMemorySize, SMTOT);

    k_prep<<<(int)(((size_t)NN * CIN + 255) / 256), 256>>>(h, fc, mask, wout);

    dim3 gm(CIN / 128, (NN + 127) / 128, PP);
    k_mma<<<gm, 256, SMTOT>>>(al, ar);

    k_hist<<<dim3((EE + 255) / 256, 1, PP), 256>>>(dst);
    k_scanA<<<dim3(49, 1, PP), 1024>>>();
    k_scanB<<<dim3(1, 1, PP), 64>>>();
    k_scanC<<<dim3(49, 1, PP), 1024>>>();
    k_fill<<<dim3((EE + 255) / 256, 1, PP), 256>>>(dst, src);

    for (int p = 0; p < PP; p++)
        k_gat<<<NN / 8, 256>>>(p, h, attn);

    k_bnfin<<<dim3(1, 1, PP), 256>>>(gamma, beta);
    k_pool<<<(NN * 64 + 255) / 256, 256>>>(wout, pooled);
}

// round 15
// speedup vs baseline: 1.6669x; 1.0532x over previous
#include <cuda_runtime.h>
#include <cuda_bf16.h>
#include <cuda_fp16.h>
#include <cstdint>

#define NN   50000
#define EE   800000
#define PP   3
#define HH   4
#define DD   64
#define CIN  256          // H*D = in_size
#define K2   256          // GEMM K (bf16 hi only; lo terms negligible)
#define EPS  1e-5f
#define SLOPE 0.2f

// ---------------- device scratch (static, no allocation) ----------------
__device__ __align__(256) __half g_f16 [(size_t)PP*NN*CIN];   // fp16 projected features
__device__ __align__(256) float g_accum[(size_t)PP*NN*CIN];
__device__ __align__(256) __nv_bfloat16 g_h2 [(size_t)NN*K2];
__device__ __align__(256) __nv_bfloat16 g_w2t[(size_t)PP*CIN*K2];
__device__ __align__(16)  float g_el   [PP*NN*HH];
__device__ __align__(16)  float g_er   [PP*NN*HH];
__device__ int g_deg   [PP*NN];
__device__ int g_rowptr[PP*(NN+1)];
__device__ int g_cur   [PP*NN];
__device__ int g_bsum  [PP*64];
__device__ int g_boff  [PP*64];
__device__ int g_eidx  [(size_t)PP*EE];
__device__ int g_esrc  [(size_t)PP*EE];
__device__ float g_sum  [PP*CIN];
__device__ float g_sumsq[PP*CIN];
__device__ float g_scale[PP*CIN];
__device__ float g_shift[PP*CIN];

// ---------------- K_prep: fused zero + weights + conversions ----------------
__global__ void k_prep(const float* __restrict__ h, const float* __restrict__ fc,
                       const float* __restrict__ mask, float* __restrict__ wout) {
    size_t i = (size_t)blockIdx.x * blockDim.x + threadIdx.x;
    if (i < (size_t)NN * CIN)
        g_h2[i] = __float2bfloat16(h[i]);
    if (i < PP * CIN * CIN) {
        int p = (int)(i >> 16), rem = (int)(i & 65535);
        int k = rem >> 8, n = rem & 255;
        g_w2t[((size_t)p * CIN + n) * K2 + k] = __float2bfloat16(fc[i]);
    }
    if (i < PP * NN) g_deg[i] = 0;
    if (i < PP * CIN) { g_sum[i] = 0.f; g_sumsq[i] = 0.f; }
    if (i < NN) {
        float m0 = mask[i*PP+0], m1 = mask[i*PP+1], m2 = mask[i*PP+2];
        float inv = 1.f / (m0 + m1 + m2);
        wout[i*PP+0] = m0 * inv;
        wout[i*PP+1] = m1 * inv;
        wout[i*PP+2] = m2 * inv;
    }
}

// ---------------- K1: HMMA bf16 GEMM, cp.async + ldmatrix ----------------
#define BKK 64
#define ASTR 72                         // bf16 units; 144 B row stride
#define SZA (128 * ASTR * 2)            // 18432 B per tile
#define BUFB (2 * SZA)                  // A + B per buffer
#define SMTOT (2 * BUFB)                // 73728 B

__device__ __forceinline__ void mma_bf16(float* c, const uint32_t* a, const uint32_t* b) {
    asm volatile("mma.sync.aligned.m16n8k16.row.col.f32.bf16.bf16.f32 "
        "{%0,%1,%2,%3}, {%4,%5,%6,%7}, {%8,%9}, {%0,%1,%2,%3};"
        : "+f"(c[0]), "+f"(c[1]), "+f"(c[2]), "+f"(c[3])
        : "r"(a[0]), "r"(a[1]), "r"(a[2]), "r"(a[3]), "r"(b[0]), "r"(b[1]));
}
__device__ __forceinline__ void ldmx4(uint32_t* r, uint32_t addr) {
    asm volatile("ldmatrix.sync.aligned.m8n8.x4.shared.b16 {%0,%1,%2,%3}, [%4];"
        : "=r"(r[0]), "=r"(r[1]), "=r"(r[2]), "=r"(r[3]) : "r"(addr));
}
__device__ __forceinline__ void cp16(uint32_t dst, const void* src, bool valid) {
    int sz = valid ? 16 : 0;
    asm volatile("cp.async.cg.shared.global [%0], [%1], 16, %2;"
                 :: "r"(dst), "l"(src), "r"(sz));
}
__device__ __forceinline__ uint32_t cvta_s(const void* p) {
    uint32_t a;
    asm("{ .reg .u64 t; cvta.to.shared.u64 t, %1; cvt.u32.u64 %0, t; }" : "=r"(a) : "l"(p));
    return a;
}

__global__ void __launch_bounds__(256) k_mma(
    const float* __restrict__ al, const float* __restrict__ ar_) {
    extern __shared__ __align__(16) char dsm[];
    uint32_t sm0 = cvta_s(dsm);

    int p = blockIdx.z;
    int m0 = blockIdx.y * 128, n0 = blockIdx.x * 128;
    int tid = threadIdx.x, wid = tid >> 5, lane = tid & 31;
    int wm = wid & 3, wn = wid >> 2;
    int grp = lane >> 2, tg = lane & 3;

    // per-lane ldmatrix byte offsets (within buffer)
    int rlA = (lane & 7) + ((lane >> 3) & 1) * 8;    // row-in-16 for A matrices
    int kbA = ((lane >> 4) & 1) * 16;                // k byte off (0 or 16)
    uint32_t aoff0 = (uint32_t)((wm * 32 +      rlA) * 144 + kbA);
    uint32_t aoff1 = (uint32_t)((wm * 32 + 16 + rlA) * 144 + kbA);
    int gB = lane >> 3;
    int rlB = lane & 7;
    int ntl = gB >> 1;                                // 0/1 within pair
    int kbB = (gB & 1) * 16;
    uint32_t boff[4];
    #pragma unroll
    for (int j = 0; j < 4; j++)
        boff[j] = (uint32_t)((wn * 64 + (2 * j + ntl) * 8 + rlB) * 144 + kbB);

    float acc[2][8][4];
    #pragma unroll
    for (int ms = 0; ms < 2; ms++)
        #pragma unroll
        for (int nt = 0; nt < 8; nt++)
            #pragma unroll
            for (int q = 0; q < 4; q++) acc[ms][nt][q] = 0.f;

    auto load_tile = [&](int kb, int buf) {
        uint32_t base = sm0 + buf * BUFB;
        #pragma unroll
        for (int t = 0; t < 4; t++) {
            int c = tid + t * 256;
            int row = c >> 3, seg = c & 7;
            int gm = m0 + row;
            cp16(base + row * 144 + seg * 16,
                 g_h2 + (size_t)gm * K2 + kb * BKK + seg * 8, gm < NN);
            cp16(base + SZA + row * 144 + seg * 16,
                 g_w2t + ((size_t)p * CIN + n0 + row) * K2 + kb * BKK + seg * 8, true);
        }
    };

    load_tile(0, 0);
    asm volatile("cp.async.commit_group;");

    for (int kb = 0; kb < K2 / BKK; kb++) {
        if (kb + 1 < K2 / BKK) load_tile(kb + 1, (kb + 1) & 1);
        asm volatile("cp.async.commit_group;");
        asm volatile("cp.async.wait_group 1;");
        __syncthreads();

        uint32_t sA32 = sm0 + (kb & 1) * BUFB;
        uint32_t sB32 = sA32 + SZA;

        #pragma unroll
        for (int ks = 0; ks < BKK / 16; ks++) {
            uint32_t k0b = ks * 32;                   // 16 halves = 32 bytes
            uint32_t afr[2][4];
            ldmx4(afr[0], sA32 + aoff0 + k0b);
            ldmx4(afr[1], sA32 + aoff1 + k0b);
            uint32_t bq[4][4];
            #pragma unroll
            for (int j = 0; j < 4; j++)
                ldmx4(bq[j], sB32 + boff[j] + k0b);
            #pragma unroll
            for (int ms = 0; ms < 2; ms++)
                #pragma unroll
                for (int nt = 0; nt < 8; nt++)
                    mma_bf16(acc[ms][nt], afr[ms], &bq[nt >> 1][(nt & 1) * 2]);
        }
        __syncthreads();
    }

    // epilogue: store fp16 feat + fused el/er (warp tile spans exactly one head)
    int head = (n0 >> 6) + wn;
    float alv[16], arv[16];
    #pragma unroll
    for (int nt = 0; nt < 8; nt++) {
        int d = nt * 8 + tg * 2;
        alv[nt*2+0] = al [(size_t)p * CIN + head * DD + d];
        alv[nt*2+1] = al [(size_t)p * CIN + head * DD + d + 1];
        arv[nt*2+0] = ar_[(size_t)p * CIN + head * DD + d];
        arv[nt*2+1] = ar_[(size_t)p * CIN + head * DD + d + 1];
    }
    #pragma unroll
    for (int ms = 0; ms < 2; ms++) {
        int r0 = m0 + wm * 32 + ms * 16 + grp;
        int r1 = r0 + 8;
        float el0 = 0.f, er0 = 0.f, el1 = 0.f, er1 = 0.f;
        #pragma unroll
        for (int nt = 0; nt < 8; nt++) {
            float c0 = acc[ms][nt][0], c1 = acc[ms][nt][1];
            float c2 = acc[ms][nt][2], c3 = acc[ms][nt][3];
            el0 += c0 * alv[nt*2] + c1 * alv[nt*2+1];
            er0 += c0 * arv[nt*2] + c1 * arv[nt*2+1];
            el1 += c2 * alv[nt*2] + c3 * alv[nt*2+1];
            er1 += c2 * arv[nt*2] + c3 * arv[nt*2+1];
            int col = n0 + wn * 64 + nt * 8 + tg * 2;
            if (r0 < NN)
                *(__half2*)(g_f16 + ((size_t)p * NN + r0) * CIN + col) = __floats2half2_rn(c0, c1);
            if (r1 < NN)
                *(__half2*)(g_f16 + ((size_t)p * NN + r1) * CIN + col) = __floats2half2_rn(c2, c3);
        }
        #pragma unroll
        for (int off = 1; off < 4; off <<= 1) {
            el0 += __shfl_xor_sync(0xffffffffu, el0, off);
            er0 += __shfl_xor_sync(0xffffffffu, er0, off);
            el1 += __shfl_xor_sync(0xffffffffu, el1, off);
            er1 += __shfl_xor_sync(0xffffffffu, er1, off);
        }
        if (tg == 0) {
            if (r0 < NN) {
                g_el[((size_t)p * NN + r0) * HH + head] = el0;
                g_er[((size_t)p * NN + r0) * HH + head] = er0;
            }
            if (r1 < NN) {
                g_el[((size_t)p * NN + r1) * HH + head] = el1;
                g_er[((size_t)p * NN + r1) * HH + head] = er1;
            }
        }
    }
}

// ---------------- CSR build ----------------
__global__ void k_hist(const int* __restrict__ dst) {
    int e = blockIdx.x * blockDim.x + threadIdx.x;
    int p = blockIdx.z;
    if (e < EE) atomicAdd(&g_deg[p * NN + dst[(size_t)p * EE + e]], 1);
}

__device__ __forceinline__ int warp_incl_scan(int v, int lane) {
    #pragma unroll
    for (int off = 1; off < 32; off <<= 1) {
        int t = __shfl_up_sync(0xffffffffu, v, off);
        if (lane >= off) v += t;
    }
    return v;
}

__global__ void k_scanA() {
    int p = blockIdx.z, b = blockIdx.x, tid = threadIdx.x;
    int lane = tid & 31, wid = tid >> 5;
    __shared__ int ws[32];
    int idx = b * 1024 + tid;
    int v = (idx < NN) ? g_deg[p * NN + idx] : 0;
    #pragma unroll
    for (int off = 16; off; off >>= 1) v += __shfl_xor_sync(0xffffffffu, v, off);
    if (lane == 0) ws[wid] = v;
    __syncthreads();
    if (wid == 0) {
        int s = ws[lane];
        #pragma unroll
        for (int off = 16; off; off >>= 1) s += __shfl_xor_sync(0xffffffffu, s, off);
        if (lane == 0) g_bsum[p * 64 + b] = s;
    }
}
__global__ void k_scanB() {
    int p = blockIdx.z, tid = threadIdx.x;   // 64 threads
    int lane = tid & 31, w = tid >> 5;
    __shared__ int t0;
    int v = (tid < 49) ? g_bsum[p * 64 + tid] : 0;
    int sc = warp_incl_scan(v, lane);
    if (w == 0 && lane == 31) t0 = sc;
    __syncthreads();
    int incl = sc + (w == 1 ? t0 : 0);
    g_boff[p * 64 + tid] = incl - v;
}
__global__ void k_scanC() {
    int p = blockIdx.z, b = blockIdx.x, tid = threadIdx.x;
    int lane = tid & 31, wid = tid >> 5;
    __shared__ int ws[32];
    int idx = b * 1024 + tid;
    int v = (idx < NN) ? g_deg[p * NN + idx] : 0;
    int sc = warp_incl_scan(v, lane);
    if (lane == 31) ws[wid] = sc;
    __syncthreads();
    if (wid == 0) ws[lane] = warp_incl_scan(ws[lane], lane);
    __syncthreads();
    int incl = sc + (wid > 0 ? ws[wid - 1] : 0) + g_boff[p * 64 + b];
    if (idx < NN) {
        g_rowptr[p * (NN + 1) + idx + 1] = incl;
        g_cur[p * NN + idx] = incl - v;
    }
    if (b == 0 && tid == 0) g_rowptr[p * (NN + 1)] = 0;
}

__global__ void k_fill(const int* __restrict__ dst, const int* __restrict__ src) {
    int e = blockIdx.x * blockDim.x + threadIdx.x;
    int p = blockIdx.z;
    if (e >= EE) return;
    int d = dst[(size_t)p * EE + e];
    int pos = atomicAdd(&g_cur[p * NN + d], 1);
    g_eidx[(size_t)p * EE + pos] = e;
    g_esrc[(size_t)p * EE + pos] = src[(size_t)p * EE + e];
}

// ---------------- K5: fused GAT per dst node (warp per node) + BN stats ----------------
__device__ __forceinline__ float lrelu(float v) { return v > 0.f ? v : SLOPE * v; }
#define ONLINE_UPD(v, m, d) \
    do { if ((v) > (m)) { (d) = (d) * __expf((m) - (v)) + 1.f; (m) = (v); } \
         else (d) += __expf((v) - (m)); } while (0)
#define CAP 64

__global__ void __launch_bounds__(256) k_gat(
    const float* __restrict__ h, float* __restrict__ attn_out) {
    __shared__ float s_v  [8][CAP][4];   // cached leaky-relu scores (pass A -> pass B)
    __shared__ int   s_src[8][CAP];      // cached src ids
    __shared__ float s_a  [8][32][4];    // per-block alphas
    __shared__ float s_x  [8][CIN];      // BN transpose-reduce buffer

    int p = blockIdx.z;
    int tid = threadIdx.x;
    int lane = tid & 31, wid = tid >> 5;
    int n = blockIdx.x * 8 + wid;        // NN = 6250 * 8, always < NN
    int beg = g_rowptr[p * (NN + 1) + n];
    int end = g_rowptr[p * (NN + 1) + n + 1];
    int myhead = lane >> 3;

    float acc[8];
    #pragma unroll
    for (int q = 0; q < 8; q++) acc[q] = 0.f;

    if (end > beg) {
        float4 er4 = *(const float4*)(g_er + ((size_t)p * NN + n) * HH);

        // pass A: online softmax + cache v/src in smem
        float m0 = -1e30f, m1 = -1e30f, m2 = -1e30f, m3 = -1e30f;
        float d0 = 0.f, d1 = 0.f, d2 = 0.f, d3 = 0.f;
        for (int j = beg + lane; j < end; j += 32) {
            int s = g_esrc[(size_t)p * EE + j];
            float4 el4 = *(const float4*)(g_el + ((size_t)p * NN + s) * HH);
            float v0 = lrelu(el4.x + er4.x), v1 = lrelu(el4.y + er4.y);
            float v2 = lrelu(el4.z + er4.z), v3 = lrelu(el4.w + er4.w);
            int slot = j - beg;
            if (slot < CAP) {
                s_src[wid][slot] = s;
                *(float4*)s_v[wid][slot] = make_float4(v0, v1, v2, v3);
            }
            ONLINE_UPD(v0, m0, d0); ONLINE_UPD(v1, m1, d1);
            ONLINE_UPD(v2, m2, d2); ONLINE_UPD(v3, m3, d3);
        }
        float M0 = m0, M1 = m1, M2 = m2, M3 = m3;
        #pragma unroll
        for (int off = 16; off; off >>= 1) {
            M0 = fmaxf(M0, __shfl_xor_sync(0xffffffffu, M0, off));
            M1 = fmaxf(M1, __shfl_xor_sync(0xffffffffu, M1, off));
            M2 = fmaxf(M2, __shfl_xor_sync(0xffffffffu, M2, off));
            M3 = fmaxf(M3, __shfl_xor_sync(0xffffffffu, M3, off));
        }
        d0 *= __expf(m0 - M0); d1 *= __expf(m1 - M1);
        d2 *= __expf(m2 - M2); d3 *= __expf(m3 - M3);
        #pragma unroll
        for (int off = 16; off; off >>= 1) {
            d0 += __shfl_xor_sync(0xffffffffu, d0, off);
            d1 += __shfl_xor_sync(0xffffffffu, d1, off);
            d2 += __shfl_xor_sync(0xffffffffu, d2, off);
            d3 += __shfl_xor_sync(0xffffffffu, d3, off);
        }
        float i0 = d0 > 0.f ? 1.f / d0 : 0.f;
        float i1 = d1 > 0.f ? 1.f / d1 : 0.f;
        float i2 = d2 > 0.f ? 1.f / d2 : 0.f;
        float i3 = d3 > 0.f ? 1.f / d3 : 0.f;

        // pass B blocks of 32 edges
        for (int jb = beg; jb < end; jb += 32) {
            int j = jb + lane;
            int sj = 0;
            if (j < end) {
                int slot = j - beg;
                float4 v4;
                if (slot < CAP) {
                    v4 = *(const float4*)s_v[wid][slot];
                    sj = s_src[wid][slot];
                } else {                                  // ultra-rare overflow
                    sj = g_esrc[(size_t)p * EE + j];
                    float4 el4 = *(const float4*)(g_el + ((size_t)p * NN + sj) * HH);
                    v4 = make_float4(lrelu(el4.x + er4.x), lrelu(el4.y + er4.y),
                                     lrelu(el4.z + er4.z), lrelu(el4.w + er4.w));
                }
                float a0 = __expf(v4.x - M0) * i0;
                float a1 = __expf(v4.y - M1) * i1;
                float a2 = __expf(v4.z - M2) * i2;
                float a3 = __expf(v4.w - M3) * i3;
                *(float4*)s_a[wid][lane] = make_float4(a0, a1, a2, a3);
                int eid = g_eidx[(size_t)p * EE + j];
                attn_out[(size_t)p * EE + eid] = 0.25f * (a0 + a1 + a2 + a3);
            }
            __syncwarp();
            int cnt = min(32, end - jb);
            int tb = jb - beg;
            const __half* fbase = g_f16 + (size_t)p * NN * CIN;
            int t = 0;
            for (; t + 3 < cnt; t += 4) {
                int s0, s1, s2, s3;
                int t0g = tb + t;
                if (t0g + 3 < CAP) {
                    s0 = s_src[wid][t0g];     s1 = s_src[wid][t0g + 1];
                    s2 = s_src[wid][t0g + 2]; s3 = s_src[wid][t0g + 3];
                } else {
                    s0 = __shfl_sync(0xffffffffu, sj, t);
                    s1 = __shfl_sync(0xffffffffu, sj, t + 1);
                    s2 = __shfl_sync(0xffffffffu, sj, t + 2);
                    s3 = __shfl_sync(0xffffffffu, sj, t + 3);
                }
                uint4 q0 = ((const uint4*)(fbase + (size_t)s0 * CIN))[lane];
                uint4 q1 = ((const uint4*)(fbase + (size_t)s1 * CIN))[lane];
                uint4 q2 = ((const uint4*)(fbase + (size_t)s2 * CIN))[lane];
                uint4 q3 = ((const uint4*)(fbase + (size_t)s3 * CIN))[lane];
                float w0 = s_a[wid][t][myhead];
                float w1 = s_a[wid][t + 1][myhead];
                float w2 = s_a[wid][t + 2][myhead];
                float w3 = s_a[wid][t + 3][myhead];
                const __half2* ha = (const __half2*)&q0;
                const __half2* hb = (const __half2*)&q1;
                const __half2* hc = (const __half2*)&q2;
                const __half2* hd = (const __half2*)&q3;
                #pragma unroll
                for (int q = 0; q < 4; q++) {
                    float2 ua = __half22float2(ha[q]);
                    float2 ub = __half22float2(hb[q]);
                    float2 uc = __half22float2(hc[q]);
                    float2 ud = __half22float2(hd[q]);
                    acc[q*2+0] += ua.x * w0 + ub.x * w1 + uc.x * w2 + ud.x * w3;
                    acc[q*2+1] += ua.y * w0 + ub.y * w1 + uc.y * w2 + ud.y * w3;
                }
            }
            for (; t < cnt; t++) {
                int t0g = tb + t;
                int s0 = (t0g < CAP) ? s_src[wid][t0g] : __shfl_sync(0xffffffffu, sj, t);
                uint4 q0 = ((const uint4*)(fbase + (size_t)s0 * CIN))[lane];
                float w0 = s_a[wid][t][myhead];
                const __half2* ha = (const __half2*)&q0;
                #pragma unroll
                for (int q = 0; q < 4; q++) {
                    float2 ua = __half22float2(ha[q]);
                    acc[q*2+0] += ua.x * w0;
                    acc[q*2+1] += ua.y * w0;
                }
            }
            __syncwarp();
        }
    }

    // epilogue: x = relu(out) + h over channels lane*8..+8
    int cb = lane * 8;
    float4 h0 = *(const float4*)(h + (size_t)n * CIN + cb);
    float4 h1 = *(const float4*)(h + (size_t)n * CIN + cb + 4);
    float x[8];
    x[0] = fmaxf(acc[0], 0.f) + h0.x; x[1] = fmaxf(acc[1], 0.f) + h0.y;
    x[2] = fmaxf(acc[2], 0.f) + h0.z; x[3] = fmaxf(acc[3], 0.f) + h0.w;
    x[4] = fmaxf(acc[4], 0.f) + h1.x; x[5] = fmaxf(acc[5], 0.f) + h1.y;
    x[6] = fmaxf(acc[6], 0.f) + h1.z; x[7] = fmaxf(acc[7], 0.f) + h1.w;
    float* op = g_accum + ((size_t)p * NN + n) * CIN + cb;
    *(float4*)(op)     = make_float4(x[0], x[1], x[2], x[3]);
    *(float4*)(op + 4) = make_float4(x[4], x[5], x[6], x[7]);

    // BN stats: transpose-reduce through smem (no smem atomics)
    *(float4*)&s_x[wid][cb]     = make_float4(x[0], x[1], x[2], x[3]);
    *(float4*)&s_x[wid][cb + 4] = make_float4(x[4], x[5], x[6], x[7]);
    __syncthreads();
    float ssum = 0.f, ssq = 0.f;
    #pragma unroll
    for (int w = 0; w < 8; w++) {
        float v = s_x[w][tid];
        ssum += v; ssq += v * v;
    }
    atomicAdd(&g_sum[p * CIN + tid], ssum);
    atomicAdd(&g_sumsq[p * CIN + tid], ssq);
}

// ---------------- K7: BN affine ----------------
__global__ void k_bnfin(const float* __restrict__ gamma, const float* __restrict__ beta) {
    int p = blockIdx.z; int c = threadIdx.x;
    float mu  = g_sum[p * CIN + c] * (1.f / NN);
    float var = g_sumsq[p * CIN + c] * (1.f / NN) - mu * mu;
    float sc = gamma[c] * rsqrtf(var + EPS);
    g_scale[p * CIN + c] = sc;
    g_shift[p * CIN + c] = beta[c] - sc * mu;
}

// ---------------- K8: pooled output ----------------
__global__ void k_pool(const float* __restrict__ wmat, float* __restrict__ pooled) {
    int idx = blockIdx.x * blockDim.x + threadIdx.x;
    if (idx >= NN * 64) return;
    int n = idx >> 6, c4 = (idx & 63) * 4;
    float4 acc = make_float4(0.f, 0.f, 0.f, 0.f);
    #pragma unroll
    for (int p = 0; p < PP; p++) {
        float wv = wmat[n * PP + p];
        float4 x  = *(const float4*)(g_accum + ((size_t)p * NN + n) * CIN + c4);
        float4 sc = *(const float4*)(g_scale + p * CIN + c4);
        float4 sh = *(const float4*)(g_shift + p * CIN + c4);
        acc.x += wv * (sc.x * x.x + sh.x);
        acc.y += wv * (sc.y * x.y + sh.y);
        acc.z += wv * (sc.z * x.z + sh.z);
        acc.w += wv * (sc.w * x.w + sh.w);
    }
    *(float4*)(pooled + (size_t)n * CIN + c4) = acc;
}

// ---------------- host ----------------
extern "C" void kernel_launch(void* const* d_in, const int* in_sizes, int n_in,
                              void* d_out, int out_size) {
    const float* h     = (const float*)d_in[0];
    const float* mask  = (const float*)d_in[1];
    const int*   src   = (const int*)  d_in[2];
    const int*   dst   = (const int*)  d_in[3];
    const float* fc    = (const float*)d_in[4];
    const float* al    = (const float*)d_in[5];
    const float* ar    = (const float*)d_in[6];
    const float* gamma = (const float*)d_in[7];
    const float* beta  = (const float*)d_in[8];

    float* out    = (float*)d_out;
    float* pooled = out;
    float* wout   = out + (size_t)NN * CIN;
    float* attn   = wout + (size_t)NN * PP;

    static cudaStream_t s2 = nullptr;
    static cudaEvent_t ev_fork = nullptr, ev_join = nullptr;
    if (!s2) {
        cudaFuncSetAttribute(k_mma, cudaFuncAttributeMaxDynamicSharedMemorySize, SMTOT);
        cudaStreamCreateWithFlags(&s2, cudaStreamNonBlocking);
        cudaEventCreateWithFlags(&ev_fork, cudaEventDisableTiming);
        cudaEventCreateWithFlags(&ev_join, cudaEventDisableTiming);
    }

    k_prep<<<(int)(((size_t)NN * CIN + 255) / 256), 256>>>(h, fc, mask, wout);

    // fork: CSR build on s2, concurrent with GEMM on main stream
    cudaEventRecord(ev_fork, 0);
    cudaStreamWaitEvent(s2, ev_fork, 0);
    k_hist<<<dim3((EE + 255) / 256, 1, PP), 256, 0, s2>>>(dst);
    k_scanA<<<dim3(49, 1, PP), 1024, 0, s2>>>();
    k_scanB<<<dim3(1, 1, PP), 64, 0, s2>>>();
    k_scanC<<<dim3(49, 1, PP), 1024, 0, s2>>>();
    k_fill<<<dim3((EE + 255) / 256, 1, PP), 256, 0, s2>>>(dst, src);
    cudaEventRecord(ev_join, s2);

    dim3 gm(CIN / 128, (NN + 127) / 128, PP);
    k_mma<<<gm, 256, SMTOT>>>(al, ar);

    // join, then all 3 paths' GAT concurrently in one launch
    cudaStreamWaitEvent(0, ev_join, 0);
    k_gat<<<dim3(NN / 8, 1, PP), 256>>>(h, attn);

    k_bnfin<<<dim3(1, 1, PP), 256>>>(gamma, beta);
    k_pool<<<(NN * 64 + 255) / 256, 256>>>(wout, pooled);
}